// round 2
// baseline (speedup 1.0000x reference)
#include <cuda_runtime.h>
#include <math.h>

typedef unsigned long long ull;
typedef long long ll;

#define NMAX 10000
#define EMAX 100000

// scratch (static __device__ arrays: allowed; no runtime allocation)
__device__ __align__(16) float g_qt[NMAX * 20];  // per-node pre-rotated query (wdot^T q)
__device__ float g_z[NMAX];                      // softmax denominators
__device__ float g_ex[EMAX];                     // per-edge exp(dot)
__device__ __align__(16) float g_vv[EMAX * 40];  // per-edge value irreps [16 s][24 v]
__device__ int g_is64;                           // edge_index dtype flag (runtime-detected)

#define INV_SQRT3  0.5773502691896258f
#define INV_SQRT2  0.7071067811865476f
#define INV_SQRT8  0.35355339059327373f
#define INV_SQRT24 0.2041241452319315f
#define INV_SQRT32 0.17677669529663687f
#define INV_SQRT80 0.11180339887498948f

// read edge_index[pos] regardless of whether storage is int64 or int32
__device__ __forceinline__ ll eidx(const void* ei, int pos) {
    if (g_is64) return ((const ll*)ei)[pos];
    return (ll)((const int*)ei)[pos];
}

// ---------------- packed f32x2 helpers (Blackwell fma.rn.f32x2) ----------------
__device__ __forceinline__ ull pack2(float a, float b) {
    ull r; asm("mov.b64 %0, {%1,%2};" : "=l"(r) : "f"(a), "f"(b)); return r;
}
__device__ __forceinline__ void fma2(ull& acc, ull w, ull h) {
    asm("fma.rn.f32x2 %0, %1, %2, %0;" : "+l"(acc) : "l"(w), "l"(h));
}
__device__ __forceinline__ ull add2(ull a, ull b) {
    ull r; asm("add.rn.f32x2 %0, %1, %2;" : "=l"(r) : "l"(a), "l"(b)); return r;
}
__device__ __forceinline__ float2 unpack2(ull v) {
    float2 r; asm("mov.b64 {%0,%1}, %2;" : "=f"(r.x), "=f"(r.y) : "l"(v)); return r;
}

// 4 consecutive per-edge weights w[j..j+3] = sum_h h[h] * W[h*S + j..j+3]
// W in smem, uniform address across warp (broadcast, conflict-free).
template <int S>
__device__ __forceinline__ float4 wchunk(const float* Wj, const ull* hh) {
    ull a0 = 0, a1 = 0, b0 = 0, b1 = 0;
#pragma unroll
    for (int h = 0; h < 32; h += 2) {
        const ulonglong2 w0 = *reinterpret_cast<const ulonglong2*>(Wj + h * S);
        const ulonglong2 w1 = *reinterpret_cast<const ulonglong2*>(Wj + (h + 1) * S);
        fma2(a0, w0.x, hh[h]);     fma2(a1, w0.y, hh[h]);
        fma2(b0, w1.x, hh[h + 1]); fma2(b1, w1.y, hh[h + 1]);
    }
    float2 lo = unpack2(add2(a0, b0));
    float2 hi = unpack2(add2(a1, b1));
    return make_float4(lo.x, lo.y, hi.x, hi.y);
}

// hidden layer: h = silu(es @ W1 * 0.25) * (1/sqrt(32)), packed as {h,h} f32x2
__device__ __forceinline__ void compute_h(const float* __restrict__ W1,
                                          const float* __restrict__ tb, ull* hh) {
    float acc[32];
#pragma unroll
    for (int x = 0; x < 32; x++) acc[x] = 0.f;
#pragma unroll 1
    for (int i = 0; i < 16; i++) {
        const float ei = tb[i];
#pragma unroll
        for (int x = 0; x < 32; x += 4) {
            float4 w = *reinterpret_cast<const float4*>(W1 + i * 32 + x);
            acc[x + 0] += ei * w.x; acc[x + 1] += ei * w.y;
            acc[x + 2] += ei * w.z; acc[x + 3] += ei * w.w;
        }
    }
#pragma unroll
    for (int x = 0; x < 32; x++) {
        float t = acc[x] * 0.25f;                 // 1/sqrt(16) fan-in
        float s = t / (1.f + __expf(-t));         // silu
        s *= INV_SQRT32;                          // 1/sqrt(32) second-layer fan-in, folded
        hh[x] = pack2(s, s);
    }
}

// FullyConnectedTensorProduct (16x0e+8x1o) x (0e+1o) -> (O0 x0e + O1 x1o)
// weights generated on the fly from hh (packed hidden) and smem W2.
// tb: per-thread smem buffer: [0..16) es, [16..32) xs, [32..56) xv (i*3+c).
template <int O0, int O1>
__device__ __forceinline__ void tp(const float* __restrict__ W, const ull* hh,
                                   const float* tb, float shs, float sh0, float sh1, float sh2,
                                   float* outS, float* outV) {
    constexpr int S = 24 * O0 + 32 * O1;   // TP weight numel (320 or 640)
    float accS[O0];
    float t3[O1], t4[O1 * 3], accV[O1 * 3];
#pragma unroll
    for (int o = 0; o < O0; o++) accS[o] = 0.f;
#pragma unroll
    for (int o = 0; o < O1; o++) t3[o] = 0.f;
#pragma unroll
    for (int o = 0; o < O1 * 3; o++) { t4[o] = 0.f; accV[o] = 0.f; }

    // path1: (xs * shs) @ w1 -> scalars
#pragma unroll 1
    for (int i = 0; i < 16; i++) {
        const float c = tb[16 + i] * shs;
#pragma unroll
        for (int ob = 0; ob < O0; ob += 4) {
            float4 w = wchunk<S>(W + i * O0 + ob, hh);
            float wa[4] = {w.x, w.y, w.z, w.w};
#pragma unroll
            for (int t = 0; t < 4; t++) accS[ob + t] += c * wa[t];
        }
    }
    // path2: (xv . shv)/sqrt3 @ w2 -> scalars
#pragma unroll 1
    for (int i = 0; i < 8; i++) {
        const float v0 = tb[32 + i * 3], v1 = tb[33 + i * 3], v2 = tb[34 + i * 3];
        const float c = (v0 * sh0 + v1 * sh1 + v2 * sh2) * INV_SQRT3;
#pragma unroll
        for (int ob = 0; ob < O0; ob += 4) {
            float4 w = wchunk<S>(W + 16 * O0 + i * O0 + ob, hh);
            float wa[4] = {w.x, w.y, w.z, w.w};
#pragma unroll
            for (int t = 0; t < 4; t++) accS[ob + t] += c * wa[t];
        }
    }
    // path3: xs (x) shv @ w3 -> vectors (shv applied at the end)
#pragma unroll 1
    for (int i = 0; i < 16; i++) {
        const float c = tb[16 + i];
#pragma unroll
        for (int ob = 0; ob < O1; ob += 4) {
            float4 w = wchunk<S>(W + 24 * O0 + i * O1 + ob, hh);
            float wa[4] = {w.x, w.y, w.z, w.w};
#pragma unroll
            for (int t = 0; t < 4; t++) t3[ob + t] += c * wa[t];
        }
    }
    // path4: xv * shs @ w4 -> vectors (shs applied at the end)
#pragma unroll 1
    for (int i = 0; i < 8; i++) {
        const float v0 = tb[32 + i * 3], v1 = tb[33 + i * 3], v2 = tb[34 + i * 3];
#pragma unroll
        for (int ob = 0; ob < O1; ob += 4) {
            float4 w = wchunk<S>(W + 24 * O0 + 16 * O1 + i * O1 + ob, hh);
            float wa[4] = {w.x, w.y, w.z, w.w};
#pragma unroll
            for (int t = 0; t < 4; t++) {
                t4[(ob + t) * 3 + 0] += v0 * wa[t];
                t4[(ob + t) * 3 + 1] += v1 * wa[t];
                t4[(ob + t) * 3 + 2] += v2 * wa[t];
            }
        }
    }
    // path5: cross(xv, shv)/sqrt2 @ w5 -> vectors
#pragma unroll 1
    for (int i = 0; i < 8; i++) {
        const float v0 = tb[32 + i * 3], v1 = tb[33 + i * 3], v2 = tb[34 + i * 3];
        const float p0 = (v1 * sh2 - v2 * sh1) * INV_SQRT2;
        const float p1 = (v2 * sh0 - v0 * sh2) * INV_SQRT2;
        const float p2 = (v0 * sh1 - v1 * sh0) * INV_SQRT2;
#pragma unroll
        for (int ob = 0; ob < O1; ob += 4) {
            float4 w = wchunk<S>(W + 24 * O0 + 24 * O1 + i * O1 + ob, hh);
            float wa[4] = {w.x, w.y, w.z, w.w};
#pragma unroll
            for (int t = 0; t < 4; t++) {
                accV[(ob + t) * 3 + 0] += p0 * wa[t];
                accV[(ob + t) * 3 + 1] += p1 * wa[t];
                accV[(ob + t) * 3 + 2] += p2 * wa[t];
            }
        }
    }
#pragma unroll
    for (int o = 0; o < O0; o++) outS[o] = accS[o] * INV_SQRT24;
#pragma unroll
    for (int o = 0; o < O1; o++) {
        outV[o * 3 + 0] = (t3[o] * sh0 + t4[o * 3 + 0] * shs + accV[o * 3 + 0]) * INV_SQRT32;
        outV[o * 3 + 1] = (t3[o] * sh1 + t4[o * 3 + 1] * shs + accV[o * 3 + 1]) * INV_SQRT32;
        outV[o * 3 + 2] = (t3[o] * sh2 + t4[o * 3 + 2] * shs + accV[o * 3 + 2]) * INV_SQRT32;
    }
}

// ---------------- K-1: detect edge_index storage width ----------------
// int64 values < 2^31 -> every odd 32-bit word is 0; int32 random in [0,10000) -> mostly nonzero.
__global__ void k_detect(const int* __restrict__ ei32, int twoE) {
    __shared__ int any;
    if (threadIdx.x == 0) any = 0;
    __syncthreads();
    int nchk = (twoE < 2048 ? twoE : 2048);   // first nchk/2 entries under int64 view
    for (int i = threadIdx.x; i < nchk / 2; i += blockDim.x)
        if (ei32[2 * i + 1] != 0) any = 1;
    __syncthreads();
    if (threadIdx.x == 0) g_is64 = (any == 0);
}

// ---------------- K0: zero outputs + denominators ----------------
__global__ void k_zero(float* __restrict__ out, int N) {
    int i = blockIdx.x * blockDim.x + threadIdx.x;
    if (i < N * 40) out[i] = 0.f;
    if (i < N) g_z[i] = 0.f;
}

// ---------------- K1: per-node pre-rotated queries q~ = wdot^T q ----------------
__global__ void k_query(const float* __restrict__ node_ft, const float* __restrict__ wqs,
                        const float* __restrict__ wqv, const float* __restrict__ wds,
                        const float* __restrict__ wdv, int N) {
    int n = blockIdx.x * blockDim.x + threadIdx.x;
    if (n >= N) return;
    const float* x = node_ft + (size_t)n * 40;
    float xs[16], xv[24];
#pragma unroll
    for (int i = 0; i < 16; i++) xs[i] = x[i];
#pragma unroll
    for (int i = 0; i < 24; i++) xv[i] = x[16 + i];

    float qs[8];
#pragma unroll
    for (int o = 0; o < 8; o++) qs[o] = 0.f;
#pragma unroll
    for (int i = 0; i < 16; i++) {
        const float c = xs[i];
#pragma unroll
        for (int o = 0; o < 8; o++) qs[o] += c * __ldg(wqs + i * 8 + o);
    }
#pragma unroll
    for (int o = 0; o < 8; o++) qs[o] *= 0.25f;

    float qv[12];
#pragma unroll
    for (int o = 0; o < 12; o++) qv[o] = 0.f;
#pragma unroll
    for (int i = 0; i < 8; i++) {
#pragma unroll
        for (int o = 0; o < 4; o++) {
            const float w = __ldg(wqv + i * 4 + o);
            qv[o * 3 + 0] += xv[i * 3 + 0] * w;
            qv[o * 3 + 1] += xv[i * 3 + 1] * w;
            qv[o * 3 + 2] += xv[i * 3 + 2] * w;
        }
    }
#pragma unroll
    for (int o = 0; o < 12; o++) qv[o] *= INV_SQRT8;

    float qt[20];
#pragma unroll
    for (int o = 0; o < 20; o++) qt[o] = 0.f;
#pragma unroll
    for (int i = 0; i < 8; i++) {
        const float c = qs[i];
#pragma unroll
        for (int o = 0; o < 8; o++) qt[o] += c * __ldg(wds + i * 8 + o);
    }
#pragma unroll
    for (int i = 0; i < 4; i++) {
#pragma unroll
        for (int o = 0; o < 4; o++) {
            const float w = __ldg(wdv + i * 4 + o);
            qt[8 + o * 3 + 0] += qv[i * 3 + 0] * w;
            qt[8 + o * 3 + 1] += qv[i * 3 + 1] * w;
            qt[8 + o * 3 + 2] += qv[i * 3 + 2] * w;
        }
    }
    float* dst = g_qt + (size_t)n * 20;
#pragma unroll
    for (int t = 0; t < 20; t++) dst[t] = qt[t];
}

// ---------------- K2: fused per-edge kernel ----------------
// smem (floats): W1k[512] W1v[512] W2k[10240] W2v[20480] TB[256*57]
#define SM_W1K 0
#define SM_W1V 512
#define SM_W2K 1024
#define SM_W2V 11264
#define SM_TB  31744
#define SMEM_K2_BYTES ((31744 + 256 * 57) * 4)

__global__ __launch_bounds__(256, 1) void k_edge(
    const float* __restrict__ node_ft, const void* __restrict__ ei,
    const float* __restrict__ edge_sh, const float* __restrict__ edge_scalars,
    const float* __restrict__ w1k, const float* __restrict__ w2k,
    const float* __restrict__ w1v, const float* __restrict__ w2v, int E) {
    extern __shared__ float sm[];
    const int tid = threadIdx.x;
    for (int i = tid * 4; i < 512;   i += 1024) *(float4*)(sm + SM_W1K + i) = *(const float4*)(w1k + i);
    for (int i = tid * 4; i < 512;   i += 1024) *(float4*)(sm + SM_W1V + i) = *(const float4*)(w1v + i);
    for (int i = tid * 4; i < 10240; i += 1024) *(float4*)(sm + SM_W2K + i) = *(const float4*)(w2k + i);
    for (int i = tid * 4; i < 20480; i += 1024) *(float4*)(sm + SM_W2V + i) = *(const float4*)(w2v + i);
    __syncthreads();

    const int e = blockIdx.x * 256 + tid;
    if (e >= E) return;

    const ll snd = eidx(ei, e);
    const ll rcv = eidx(ei, E + e);
    float* tb = sm + SM_TB + tid * 57;   // stride 57: gcd(57,32)=1 -> conflict-free

    {   // stage per-edge inputs into the padded smem buffer
        const float4* p = (const float4*)(edge_scalars + (size_t)e * 16);
        float4 a = p[0], b = p[1], c = p[2], d = p[3];
        tb[0] = a.x;  tb[1] = a.y;  tb[2] = a.z;  tb[3] = a.w;
        tb[4] = b.x;  tb[5] = b.y;  tb[6] = b.z;  tb[7] = b.w;
        tb[8] = c.x;  tb[9] = c.y;  tb[10] = c.z; tb[11] = c.w;
        tb[12] = d.x; tb[13] = d.y; tb[14] = d.z; tb[15] = d.w;
        const float4* q = (const float4*)(node_ft + (size_t)snd * 40);
#pragma unroll
        for (int t = 0; t < 10; t++) {
            float4 v = q[t];
            tb[16 + t * 4 + 0] = v.x; tb[16 + t * 4 + 1] = v.y;
            tb[16 + t * 4 + 2] = v.z; tb[16 + t * 4 + 3] = v.w;
        }
    }
    const float4 shq = *(const float4*)(edge_sh + (size_t)e * 4);
    const float shs = shq.x, sh0 = shq.y, sh1 = shq.z, sh2 = shq.w;

    ull hh[32];

    // ---- K tensor product + attention logit ----
    compute_h(sm + SM_W1K, tb, hh);
    float ks[8], kv[12];
    tp<8, 4>(sm + SM_W2K, hh, tb, shs, sh0, sh1, sh2, ks, kv);

    const float* qt = g_qt + (size_t)rcv * 20;
    const float4 q0 = *(const float4*)(qt + 0);
    const float4 q1 = *(const float4*)(qt + 4);
    const float4 q2 = *(const float4*)(qt + 8);
    const float4 q3 = *(const float4*)(qt + 12);
    const float4 q4 = *(const float4*)(qt + 16);
    float dS = q0.x * ks[0] + q0.y * ks[1] + q0.z * ks[2] + q0.w * ks[3]
             + q1.x * ks[4] + q1.y * ks[5] + q1.z * ks[6] + q1.w * ks[7];
    float dV = q2.x * kv[0] + q2.y * kv[1] + q2.z * kv[2] + q2.w * kv[3]
             + q3.x * kv[4] + q3.y * kv[5] + q3.z * kv[6] + q3.w * kv[7]
             + q4.x * kv[8] + q4.y * kv[9] + q4.z * kv[10] + q4.w * kv[11];
    const float dot = (dS + dV * INV_SQRT3) * INV_SQRT80;
    const float exv = __expf(dot);
    g_ex[e] = exv;
    atomicAdd(&g_z[rcv], exv);

    // ---- V tensor product ----
    compute_h(sm + SM_W1V, tb, hh);
    float vs[16], vv[24];
    tp<16, 8>(sm + SM_W2V, hh, tb, shs, sh0, sh1, sh2, vs, vv);

    float* dst = g_vv + (size_t)e * 40;
    *(float4*)(dst + 0)  = make_float4(vs[0], vs[1], vs[2], vs[3]);
    *(float4*)(dst + 4)  = make_float4(vs[4], vs[5], vs[6], vs[7]);
    *(float4*)(dst + 8)  = make_float4(vs[8], vs[9], vs[10], vs[11]);
    *(float4*)(dst + 12) = make_float4(vs[12], vs[13], vs[14], vs[15]);
#pragma unroll
    for (int t = 0; t < 6; t++)
        *(float4*)(dst + 16 + t * 4) =
            make_float4(vv[t * 4 + 0], vv[t * 4 + 1], vv[t * 4 + 2], vv[t * 4 + 3]);
}

// ---------------- K3: softmax normalize + scatter ----------------
__global__ void k_scatter(const void* __restrict__ ei, float* __restrict__ out, int E) {
    int e = blockIdx.x * blockDim.x + threadIdx.x;
    if (e >= E) return;
    const ll r = eidx(ei, E + e);
    const float a = sqrtf(g_ex[e] / g_z[r]);   // alpha>0 so relu is a no-op
    const float4* v = (const float4*)(g_vv + (size_t)e * 40);
    float* o = out + (size_t)r * 40;
#pragma unroll
    for (int t = 0; t < 10; t++) {
        float4 w = v[t];
        atomicAdd(o + t * 4 + 0, a * w.x);
        atomicAdd(o + t * 4 + 1, a * w.y);
        atomicAdd(o + t * 4 + 2, a * w.z);
        atomicAdd(o + t * 4 + 3, a * w.w);
    }
}

extern "C" void kernel_launch(void* const* d_in, const int* in_sizes, int n_in,
                              void* d_out, int out_size) {
    const float* node_ft      = (const float*)d_in[0];
    const void*  ei           = d_in[1];
    const float* edge_sh      = (const float*)d_in[2];
    const float* edge_scalars = (const float*)d_in[3];
    const float* wqs          = (const float*)d_in[4];
    const float* wqv          = (const float*)d_in[5];
    const float* fckw1        = (const float*)d_in[6];
    const float* fckw2        = (const float*)d_in[7];
    const float* fcvw1        = (const float*)d_in[8];
    const float* fcvw2        = (const float*)d_in[9];
    const float* wds          = (const float*)d_in[10];
    const float* wdv          = (const float*)d_in[11];
    float* out = (float*)d_out;

    const int N = in_sizes[0] / 40;
    const int E = in_sizes[1] / 2;

    cudaFuncSetAttribute(k_edge, cudaFuncAttributeMaxDynamicSharedMemorySize, SMEM_K2_BYTES);

    k_detect<<<1, 256>>>((const int*)ei, 2 * E);
    k_zero<<<(N * 40 + 255) / 256, 256>>>(out, N);
    k_query<<<(N + 255) / 256, 256>>>(node_ft, wqs, wqv, wds, wdv, N);
    k_edge<<<(E + 255) / 256, 256, SMEM_K2_BYTES>>>(node_ft, ei, edge_sh, edge_scalars,
                                                    fckw1, fckw2, fcvw1, fcvw2, E);
    k_scatter<<<(E + 255) / 256, 256>>>(ei, out, E);
}

// round 3
// speedup vs baseline: 1.5482x; 1.5482x over previous
#include <cuda_runtime.h>
#include <math.h>

typedef unsigned long long ull;
typedef long long ll;

#define NMAX 10000
#define EMAX 100000

// scratch (static __device__ arrays: allowed; no runtime allocation)
__device__ __align__(16) float g_qt[NMAX * 20];  // per-node pre-rotated query (wdot^T q)
__device__ float g_z[NMAX];                      // softmax denominators
__device__ float g_ex[EMAX];                     // per-edge exp(dot)
__device__ __align__(16) float g_vv[EMAX * 40];  // per-edge value irreps [16 s][24 v]
__device__ int g_is64;                           // edge_index dtype flag (runtime-detected)

#define INV_SQRT3  0.5773502691896258f
#define INV_SQRT2  0.7071067811865476f
#define INV_SQRT8  0.35355339059327373f
#define INV_SQRT24 0.2041241452319315f
#define INV_SQRT32 0.17677669529663687f
#define INV_SQRT80 0.11180339887498948f

__device__ __forceinline__ ll eidx(const void* ei, int pos) {
    if (g_is64) return ((const ll*)ei)[pos];
    return (ll)((const int*)ei)[pos];
}

// ---------------- packed f32x2 helpers ----------------
__device__ __forceinline__ ull pack2(float a, float b) {
    ull r; asm("mov.b64 %0, {%1,%2};" : "=l"(r) : "f"(a), "f"(b)); return r;
}
__device__ __forceinline__ void fma2(ull& acc, ull w, ull h) {
    asm("fma.rn.f32x2 %0, %1, %2, %0;" : "+l"(acc) : "l"(w), "l"(h));
}
__device__ __forceinline__ ull add2(ull a, ull b) {
    ull r; asm("add.rn.f32x2 %0, %1, %2;" : "=l"(r) : "l"(a), "l"(b)); return r;
}
__device__ __forceinline__ float2 unpack2(ull v) {
    float2 r; asm("mov.b64 {%0,%1}, %2;" : "=f"(r.x), "=f"(r.y) : "l"(v)); return r;
}

// 4 per-edge weights w[j..j+3] = sum_h h[h] * W[h*S + j..j+3]; W smem broadcast.
template <int S>
__device__ __forceinline__ float4 wchunk(const float* Wj, const ull* hh) {
    ull a0 = 0, a1 = 0, b0 = 0, b1 = 0;
#pragma unroll
    for (int h = 0; h < 32; h += 2) {
        const ulonglong2 w0 = *reinterpret_cast<const ulonglong2*>(Wj + h * S);
        const ulonglong2 w1 = *reinterpret_cast<const ulonglong2*>(Wj + (h + 1) * S);
        fma2(a0, w0.x, hh[h]);     fma2(a1, w0.y, hh[h]);
        fma2(b0, w1.x, hh[h + 1]); fma2(b1, w1.y, hh[h + 1]);
    }
    float2 lo = unpack2(add2(a0, b0));
    float2 hi = unpack2(add2(a1, b1));
    return make_float4(lo.x, lo.y, hi.x, hi.y);
}

// hidden layer: h = silu(es @ W1 * 0.25) * (1/sqrt(32)), packed {h,h}
__device__ __forceinline__ void compute_h(const float* __restrict__ W1,
                                          const float* __restrict__ tb, ull* hh) {
    float acc[32];
#pragma unroll
    for (int x = 0; x < 32; x++) acc[x] = 0.f;
#pragma unroll 1
    for (int i = 0; i < 16; i++) {
        const float ei = tb[i];
#pragma unroll
        for (int x = 0; x < 32; x += 4) {
            float4 w = *reinterpret_cast<const float4*>(W1 + i * 32 + x);
            acc[x + 0] += ei * w.x; acc[x + 1] += ei * w.y;
            acc[x + 2] += ei * w.z; acc[x + 3] += ei * w.w;
        }
    }
#pragma unroll
    for (int x = 0; x < 32; x++) {
        float t = acc[x] * 0.25f;
        float s = t / (1.f + __expf(-t));
        s *= INV_SQRT32;
        hh[x] = pack2(s, s);
    }
}

// stage per-edge inputs into padded per-thread smem buffer (stride 57)
// [0..16) es, [16..32) xs, [32..56) xv
__device__ __forceinline__ void stage_tb(float* tb, const float* __restrict__ edge_scalars,
                                         const float* __restrict__ node_ft, int e, ll snd) {
    const float4* p = (const float4*)(edge_scalars + (size_t)e * 16);
#pragma unroll
    for (int t = 0; t < 4; t++) {
        float4 v = p[t];
        tb[t * 4 + 0] = v.x; tb[t * 4 + 1] = v.y; tb[t * 4 + 2] = v.z; tb[t * 4 + 3] = v.w;
    }
    const float4* q = (const float4*)(node_ft + (size_t)snd * 40);
#pragma unroll
    for (int t = 0; t < 10; t++) {
        float4 v = q[t];
        tb[16 + t * 4 + 0] = v.x; tb[16 + t * 4 + 1] = v.y;
        tb[16 + t * 4 + 2] = v.z; tb[16 + t * 4 + 3] = v.w;
    }
}

// ---------------- tiny kernels ----------------
__global__ void k_detect(const int* __restrict__ ei32, int twoE) {
    __shared__ int any;
    if (threadIdx.x == 0) any = 0;
    __syncthreads();
    int nchk = (twoE < 2048 ? twoE : 2048);
    for (int i = threadIdx.x; i < nchk / 2; i += blockDim.x)
        if (ei32[2 * i + 1] != 0) any = 1;
    __syncthreads();
    if (threadIdx.x == 0) g_is64 = (any == 0);
}

__global__ void k_zero(float* __restrict__ out, int N) {
    int i = blockIdx.x * blockDim.x + threadIdx.x;
    if (i < N * 40) out[i] = 0.f;
    if (i < N) g_z[i] = 0.f;
}

__global__ void k_query(const float* __restrict__ node_ft, const float* __restrict__ wqs,
                        const float* __restrict__ wqv, const float* __restrict__ wds,
                        const float* __restrict__ wdv, int N) {
    int n = blockIdx.x * blockDim.x + threadIdx.x;
    if (n >= N) return;
    const float* x = node_ft + (size_t)n * 40;
    float xs[16], xv[24];
#pragma unroll
    for (int i = 0; i < 16; i++) xs[i] = x[i];
#pragma unroll
    for (int i = 0; i < 24; i++) xv[i] = x[16 + i];

    float qs[8];
#pragma unroll
    for (int o = 0; o < 8; o++) qs[o] = 0.f;
#pragma unroll
    for (int i = 0; i < 16; i++) {
        const float c = xs[i];
#pragma unroll
        for (int o = 0; o < 8; o++) qs[o] += c * __ldg(wqs + i * 8 + o);
    }
#pragma unroll
    for (int o = 0; o < 8; o++) qs[o] *= 0.25f;

    float qv[12];
#pragma unroll
    for (int o = 0; o < 12; o++) qv[o] = 0.f;
#pragma unroll
    for (int i = 0; i < 8; i++) {
#pragma unroll
        for (int o = 0; o < 4; o++) {
            const float w = __ldg(wqv + i * 4 + o);
            qv[o * 3 + 0] += xv[i * 3 + 0] * w;
            qv[o * 3 + 1] += xv[i * 3 + 1] * w;
            qv[o * 3 + 2] += xv[i * 3 + 2] * w;
        }
    }
#pragma unroll
    for (int o = 0; o < 12; o++) qv[o] *= INV_SQRT8;

    float qt[20];
#pragma unroll
    for (int o = 0; o < 20; o++) qt[o] = 0.f;
#pragma unroll
    for (int i = 0; i < 8; i++) {
        const float c = qs[i];
#pragma unroll
        for (int o = 0; o < 8; o++) qt[o] += c * __ldg(wds + i * 8 + o);
    }
#pragma unroll
    for (int i = 0; i < 4; i++) {
#pragma unroll
        for (int o = 0; o < 4; o++) {
            const float w = __ldg(wdv + i * 4 + o);
            qt[8 + o * 3 + 0] += qv[i * 3 + 0] * w;
            qt[8 + o * 3 + 1] += qv[i * 3 + 1] * w;
            qt[8 + o * 3 + 2] += qv[i * 3 + 2] * w;
        }
    }
    float* dst = g_qt + (size_t)n * 20;
#pragma unroll
    for (int t = 0; t < 20; t++) dst[t] = qt[t];
}

// ================= K kernel: full K TP + attention logit =================
// smem floats: W1[512] W2[32*320=10240] TB[128*57]
#define KK_W1 0
#define KK_W2 512
#define KK_TB 10752
#define KK_SMEM ((10752 + 128 * 57) * 4)

__global__ __launch_bounds__(128, 3) void k_K(
    const float* __restrict__ node_ft, const void* __restrict__ ei,
    const float* __restrict__ edge_sh, const float* __restrict__ edge_scalars,
    const float* __restrict__ w1k, const float* __restrict__ w2k, int E) {
    extern __shared__ float sm[];
    const int tid = threadIdx.x;
    for (int i = tid * 4; i < 512;   i += 512) *(float4*)(sm + KK_W1 + i) = *(const float4*)(w1k + i);
    for (int i = tid * 4; i < 10240; i += 512) *(float4*)(sm + KK_W2 + i) = *(const float4*)(w2k + i);
    __syncthreads();

    const int e = blockIdx.x * 128 + tid;
    if (e >= E) return;
    const ll snd = eidx(ei, e);
    const ll rcv = eidx(ei, E + e);
    float* tb = sm + KK_TB + tid * 57;
    stage_tb(tb, edge_scalars, node_ft, e, snd);

    const float4 shq = *(const float4*)(edge_sh + (size_t)e * 4);
    const float shs = shq.x, sh0 = shq.y, sh1 = shq.z, sh2 = shq.w;

    ull hh[32];
    compute_h(sm + KK_W1, tb, hh);

    constexpr int S = 320;
    const float* W = sm + KK_W2;
    float accS[8], t3[4], t4[12], accV[12];
#pragma unroll
    for (int o = 0; o < 8; o++) accS[o] = 0.f;
#pragma unroll
    for (int o = 0; o < 4; o++) t3[o] = 0.f;
#pragma unroll
    for (int o = 0; o < 12; o++) { t4[o] = 0.f; accV[o] = 0.f; }

#pragma unroll 1
    for (int i = 0; i < 16; i++) {      // path1: scalars
        const float c = tb[16 + i] * shs;
#pragma unroll
        for (int ob = 0; ob < 8; ob += 4) {
            float4 w = wchunk<S>(W + i * 8 + ob, hh);
            accS[ob + 0] += c * w.x; accS[ob + 1] += c * w.y;
            accS[ob + 2] += c * w.z; accS[ob + 3] += c * w.w;
        }
    }
#pragma unroll 1
    for (int i = 0; i < 8; i++) {       // path2: scalars
        const float v0 = tb[32 + i * 3], v1 = tb[33 + i * 3], v2 = tb[34 + i * 3];
        const float c = (v0 * sh0 + v1 * sh1 + v2 * sh2) * INV_SQRT3;
#pragma unroll
        for (int ob = 0; ob < 8; ob += 4) {
            float4 w = wchunk<S>(W + 128 + i * 8 + ob, hh);
            accS[ob + 0] += c * w.x; accS[ob + 1] += c * w.y;
            accS[ob + 2] += c * w.z; accS[ob + 3] += c * w.w;
        }
    }
#pragma unroll 1
    for (int i = 0; i < 16; i++) {      // path3: vectors (shv applied later)
        const float c = tb[16 + i];
        float4 w = wchunk<S>(W + 192 + i * 4, hh);
        t3[0] += c * w.x; t3[1] += c * w.y; t3[2] += c * w.z; t3[3] += c * w.w;
    }
#pragma unroll 1
    for (int i = 0; i < 8; i++) {       // path4: vectors (shs applied later)
        const float v0 = tb[32 + i * 3], v1 = tb[33 + i * 3], v2 = tb[34 + i * 3];
        float4 w = wchunk<S>(W + 256 + i * 4, hh);
        float wa[4] = {w.x, w.y, w.z, w.w};
#pragma unroll
        for (int t = 0; t < 4; t++) {
            t4[t * 3 + 0] += v0 * wa[t];
            t4[t * 3 + 1] += v1 * wa[t];
            t4[t * 3 + 2] += v2 * wa[t];
        }
    }
#pragma unroll 1
    for (int i = 0; i < 8; i++) {       // path5: cross
        const float v0 = tb[32 + i * 3], v1 = tb[33 + i * 3], v2 = tb[34 + i * 3];
        const float p0 = (v1 * sh2 - v2 * sh1) * INV_SQRT2;
        const float p1 = (v2 * sh0 - v0 * sh2) * INV_SQRT2;
        const float p2 = (v0 * sh1 - v1 * sh0) * INV_SQRT2;
        float4 w = wchunk<S>(W + 288 + i * 4, hh);
        float wa[4] = {w.x, w.y, w.z, w.w};
#pragma unroll
        for (int t = 0; t < 4; t++) {
            accV[t * 3 + 0] += p0 * wa[t];
            accV[t * 3 + 1] += p1 * wa[t];
            accV[t * 3 + 2] += p2 * wa[t];
        }
    }

    float ks[8], kv[12];
#pragma unroll
    for (int o = 0; o < 8; o++) ks[o] = accS[o] * INV_SQRT24;
#pragma unroll
    for (int o = 0; o < 4; o++) {
        kv[o * 3 + 0] = (t3[o] * sh0 + t4[o * 3 + 0] * shs + accV[o * 3 + 0]) * INV_SQRT32;
        kv[o * 3 + 1] = (t3[o] * sh1 + t4[o * 3 + 1] * shs + accV[o * 3 + 1]) * INV_SQRT32;
        kv[o * 3 + 2] = (t3[o] * sh2 + t4[o * 3 + 2] * shs + accV[o * 3 + 2]) * INV_SQRT32;
    }

    const float* qt = g_qt + (size_t)rcv * 20;
    const float4 q0 = *(const float4*)(qt + 0);
    const float4 q1 = *(const float4*)(qt + 4);
    const float4 q2 = *(const float4*)(qt + 8);
    const float4 q3 = *(const float4*)(qt + 12);
    const float4 q4 = *(const float4*)(qt + 16);
    float dS = q0.x * ks[0] + q0.y * ks[1] + q0.z * ks[2] + q0.w * ks[3]
             + q1.x * ks[4] + q1.y * ks[5] + q1.z * ks[6] + q1.w * ks[7];
    float dV = q2.x * kv[0] + q2.y * kv[1] + q2.z * kv[2] + q2.w * kv[3]
             + q3.x * kv[4] + q3.y * kv[5] + q3.z * kv[6] + q3.w * kv[7]
             + q4.x * kv[8] + q4.y * kv[9] + q4.z * kv[10] + q4.w * kv[11];
    const float dot = (dS + dV * INV_SQRT3) * INV_SQRT80;
    const float exv = __expf(dot);
    g_ex[e] = exv;
    atomicAdd(&g_z[rcv], exv);
}

// ================= Vs kernel: V scalar outputs [OFF, OFF+8) =================
// compacted weights: W[h][i*8+oo], i<16 from path1 (j=i*16+OFF+oo), i>=16 path2 (j=256+(i-16)*16+OFF+oo)
// smem floats: W1[512] W2c[32*192=6144] TB[128*57]
#define VS_W1 0
#define VS_W2 512
#define VS_TB 6656
#define VS_SMEM ((6656 + 128 * 57) * 4)

template <int OFF>
__global__ __launch_bounds__(128, 4) void k_Vs(
    const float* __restrict__ node_ft, const void* __restrict__ ei,
    const float* __restrict__ edge_sh, const float* __restrict__ edge_scalars,
    const float* __restrict__ w1v, const float* __restrict__ w2v, int E) {
    extern __shared__ float sm[];
    const int tid = threadIdx.x;
    for (int i = tid * 4; i < 512; i += 512) *(float4*)(sm + VS_W1 + i) = *(const float4*)(w1v + i);
    for (int idx = tid; idx < 32 * 192; idx += 128) {
        const int h = idx / 192, t = idx % 192, i = t / 8, oo = t % 8;
        const int j = (i < 16) ? (i * 16 + OFF + oo) : (256 + (i - 16) * 16 + OFF + oo);
        sm[VS_W2 + idx] = w2v[h * 640 + j];
    }
    __syncthreads();

    const int e = blockIdx.x * 128 + tid;
    if (e >= E) return;
    const ll snd = eidx(ei, e);
    float* tb = sm + VS_TB + tid * 57;
    stage_tb(tb, edge_scalars, node_ft, e, snd);

    const float4 shq = *(const float4*)(edge_sh + (size_t)e * 4);
    const float shs = shq.x, sh0 = shq.y, sh1 = shq.z, sh2 = shq.w;

    ull hh[32];
    compute_h(sm + VS_W1, tb, hh);

    constexpr int S = 192;
    const float* W = sm + VS_W2;
    float accS[8];
#pragma unroll
    for (int o = 0; o < 8; o++) accS[o] = 0.f;

#pragma unroll 1
    for (int i = 0; i < 16; i++) {      // path1
        const float c = tb[16 + i] * shs;
#pragma unroll
        for (int ob = 0; ob < 8; ob += 4) {
            float4 w = wchunk<S>(W + i * 8 + ob, hh);
            accS[ob + 0] += c * w.x; accS[ob + 1] += c * w.y;
            accS[ob + 2] += c * w.z; accS[ob + 3] += c * w.w;
        }
    }
#pragma unroll 1
    for (int i = 0; i < 8; i++) {       // path2
        const float v0 = tb[32 + i * 3], v1 = tb[33 + i * 3], v2 = tb[34 + i * 3];
        const float c = (v0 * sh0 + v1 * sh1 + v2 * sh2) * INV_SQRT3;
#pragma unroll
        for (int ob = 0; ob < 8; ob += 4) {
            float4 w = wchunk<S>(W + (16 + i) * 8 + ob, hh);
            accS[ob + 0] += c * w.x; accS[ob + 1] += c * w.y;
            accS[ob + 2] += c * w.z; accS[ob + 3] += c * w.w;
        }
    }
    float* dst = g_vv + (size_t)e * 40 + OFF;
    *(float4*)(dst + 0) = make_float4(accS[0] * INV_SQRT24, accS[1] * INV_SQRT24,
                                      accS[2] * INV_SQRT24, accS[3] * INV_SQRT24);
    *(float4*)(dst + 4) = make_float4(accS[4] * INV_SQRT24, accS[5] * INV_SQRT24,
                                      accS[6] * INV_SQRT24, accS[7] * INV_SQRT24);
}

// ================= Vv kernel: V vector outputs (paths 3,4,5; O1=8) =================
// weights j in [384,640): contiguous 256/h. local: path3 i*8+o (0:128), path4 128+i*8+o, path5 192+i*8+o
// smem floats: W1[512] W2c[32*256=8192] TB[128*57]
#define VV_W1 0
#define VV_W2 512
#define VV_TB 8704
#define VV_SMEM ((8704 + 128 * 57) * 4)

__global__ __launch_bounds__(128, 3) void k_Vv(
    const float* __restrict__ node_ft, const void* __restrict__ ei,
    const float* __restrict__ edge_sh, const float* __restrict__ edge_scalars,
    const float* __restrict__ w1v, const float* __restrict__ w2v, int E) {
    extern __shared__ float sm[];
    const int tid = threadIdx.x;
    for (int i = tid * 4; i < 512; i += 512) *(float4*)(sm + VV_W1 + i) = *(const float4*)(w1v + i);
    for (int idx = tid; idx < 32 * 256; idx += 128) {
        const int h = idx / 256, t = idx % 256;
        sm[VV_W2 + idx] = w2v[h * 640 + 384 + t];
    }
    __syncthreads();

    const int e = blockIdx.x * 128 + tid;
    if (e >= E) return;
    const ll snd = eidx(ei, e);
    float* tb = sm + VV_TB + tid * 57;
    stage_tb(tb, edge_scalars, node_ft, e, snd);

    const float4 shq = *(const float4*)(edge_sh + (size_t)e * 4);
    const float shs = shq.x, sh0 = shq.y, sh1 = shq.z, sh2 = shq.w;

    ull hh[32];
    compute_h(sm + VV_W1, tb, hh);

    constexpr int S = 256;
    const float* W = sm + VV_W2;
    float t3[8], t4[24], accV[24];
#pragma unroll
    for (int o = 0; o < 8; o++) t3[o] = 0.f;
#pragma unroll
    for (int o = 0; o < 24; o++) { t4[o] = 0.f; accV[o] = 0.f; }

#pragma unroll 1
    for (int i = 0; i < 16; i++) {      // path3
        const float c = tb[16 + i];
#pragma unroll
        for (int ob = 0; ob < 8; ob += 4) {
            float4 w = wchunk<S>(W + i * 8 + ob, hh);
            t3[ob + 0] += c * w.x; t3[ob + 1] += c * w.y;
            t3[ob + 2] += c * w.z; t3[ob + 3] += c * w.w;
        }
    }
#pragma unroll 1
    for (int i = 0; i < 8; i++) {       // path4
        const float v0 = tb[32 + i * 3], v1 = tb[33 + i * 3], v2 = tb[34 + i * 3];
#pragma unroll
        for (int ob = 0; ob < 8; ob += 4) {
            float4 w = wchunk<S>(W + 128 + i * 8 + ob, hh);
            float wa[4] = {w.x, w.y, w.z, w.w};
#pragma unroll
            for (int t = 0; t < 4; t++) {
                t4[(ob + t) * 3 + 0] += v0 * wa[t];
                t4[(ob + t) * 3 + 1] += v1 * wa[t];
                t4[(ob + t) * 3 + 2] += v2 * wa[t];
            }
        }
    }
#pragma unroll 1
    for (int i = 0; i < 8; i++) {       // path5
        const float v0 = tb[32 + i * 3], v1 = tb[33 + i * 3], v2 = tb[34 + i * 3];
        const float p0 = (v1 * sh2 - v2 * sh1) * INV_SQRT2;
        const float p1 = (v2 * sh0 - v0 * sh2) * INV_SQRT2;
        const float p2 = (v0 * sh1 - v1 * sh0) * INV_SQRT2;
#pragma unroll
        for (int ob = 0; ob < 8; ob += 4) {
            float4 w = wchunk<S>(W + 192 + i * 8 + ob, hh);
            float wa[4] = {w.x, w.y, w.z, w.w};
#pragma unroll
            for (int t = 0; t < 4; t++) {
                accV[(ob + t) * 3 + 0] += p0 * wa[t];
                accV[(ob + t) * 3 + 1] += p1 * wa[t];
                accV[(ob + t) * 3 + 2] += p2 * wa[t];
            }
        }
    }

    float vv[24];
#pragma unroll
    for (int o = 0; o < 8; o++) {
        vv[o * 3 + 0] = (t3[o] * sh0 + t4[o * 3 + 0] * shs + accV[o * 3 + 0]) * INV_SQRT32;
        vv[o * 3 + 1] = (t3[o] * sh1 + t4[o * 3 + 1] * shs + accV[o * 3 + 1]) * INV_SQRT32;
        vv[o * 3 + 2] = (t3[o] * sh2 + t4[o * 3 + 2] * shs + accV[o * 3 + 2]) * INV_SQRT32;
    }
    float* dst = g_vv + (size_t)e * 40 + 16;
#pragma unroll
    for (int t = 0; t < 6; t++)
        *(float4*)(dst + t * 4) =
            make_float4(vv[t * 4 + 0], vv[t * 4 + 1], vv[t * 4 + 2], vv[t * 4 + 3]);
}

// ---------------- scatter: softmax normalize + vector reduction ----------------
__global__ void k_scatter(const void* __restrict__ ei, float* __restrict__ out, int E) {
    int e = blockIdx.x * blockDim.x + threadIdx.x;
    if (e >= E) return;
    const ll r = eidx(ei, E + e);
    const float a = sqrtf(g_ex[e] / g_z[r]);
    const float4* v = (const float4*)(g_vv + (size_t)e * 40);
    float* o = out + (size_t)r * 40;
#pragma unroll
    for (int t = 0; t < 10; t++) {
        float4 w = v[t];
        asm volatile("red.global.add.v4.f32 [%0], {%1, %2, %3, %4};"
                     :: "l"(o + t * 4), "f"(a * w.x), "f"(a * w.y), "f"(a * w.z), "f"(a * w.w)
                     : "memory");
    }
}

extern "C" void kernel_launch(void* const* d_in, const int* in_sizes, int n_in,
                              void* d_out, int out_size) {
    const float* node_ft      = (const float*)d_in[0];
    const void*  ei           = d_in[1];
    const float* edge_sh      = (const float*)d_in[2];
    const float* edge_scalars = (const float*)d_in[3];
    const float* wqs          = (const float*)d_in[4];
    const float* wqv          = (const float*)d_in[5];
    const float* fckw1        = (const float*)d_in[6];
    const float* fckw2        = (const float*)d_in[7];
    const float* fcvw1        = (const float*)d_in[8];
    const float* fcvw2        = (const float*)d_in[9];
    const float* wds          = (const float*)d_in[10];
    const float* wdv          = (const float*)d_in[11];
    float* out = (float*)d_out;

    const int N = in_sizes[0] / 40;
    const int E = in_sizes[1] / 2;
    const int gE = (E + 127) / 128;

    cudaFuncSetAttribute(k_K,      cudaFuncAttributeMaxDynamicSharedMemorySize, KK_SMEM);
    cudaFuncSetAttribute(k_Vs<0>,  cudaFuncAttributeMaxDynamicSharedMemorySize, VS_SMEM);
    cudaFuncSetAttribute(k_Vs<8>,  cudaFuncAttributeMaxDynamicSharedMemorySize, VS_SMEM);
    cudaFuncSetAttribute(k_Vv,     cudaFuncAttributeMaxDynamicSharedMemorySize, VV_SMEM);

    k_detect<<<1, 256>>>((const int*)ei, 2 * E);
    k_zero<<<(N * 40 + 255) / 256, 256>>>(out, N);
    k_query<<<(N + 255) / 256, 256>>>(node_ft, wqs, wqv, wds, wdv, N);
    k_K<<<gE, 128, KK_SMEM>>>(node_ft, ei, edge_sh, edge_scalars, fckw1, fckw2, E);
    k_Vs<0><<<gE, 128, VS_SMEM>>>(node_ft, ei, edge_sh, edge_scalars, fcvw1, fcvw2, E);
    k_Vs<8><<<gE, 128, VS_SMEM>>>(node_ft, ei, edge_sh, edge_scalars, fcvw1, fcvw2, E);
    k_Vv<<<gE, 128, VV_SMEM>>>(node_ft, ei, edge_sh, edge_scalars, fcvw1, fcvw2, E);
    k_scatter<<<(E + 255) / 256, 256>>>(ei, out, E);
}

// round 5
// speedup vs baseline: 1.6908x; 1.0921x over previous
#include <cuda_runtime.h>
#include <math.h>

typedef unsigned long long ull;
typedef long long ll;

#define NMAX 10000
#define EMAX 100000

__device__ __align__(16) float g_qt[NMAX * 20];  // per-node pre-rotated query
__device__ float g_z[NMAX];                      // softmax denominators
__device__ float g_ex[EMAX];                     // per-edge exp(dot)
__device__ __align__(16) float g_vv[EMAX * 40];  // per-edge value irreps
__device__ int g_is64;                           // edge_index dtype flag

#define INV_SQRT3  0.5773502691896258f
#define INV_SQRT2  0.7071067811865476f
#define INV_SQRT8  0.35355339059327373f
#define INV_SQRT24 0.2041241452319315f
#define INV_SQRT32 0.17677669529663687f
#define INV_SQRT80 0.11180339887498948f

__device__ __forceinline__ ll eidx(const void* ei, int pos) {
    if (g_is64) return ((const ll*)ei)[pos];
    return (ll)((const int*)ei)[pos];
}

// ---------------- packed f32x2 helpers ----------------
__device__ __forceinline__ ull pack2(float a, float b) {
    ull r; asm("mov.b64 %0, {%1,%2};" : "=l"(r) : "f"(a), "f"(b)); return r;
}
__device__ __forceinline__ void fma2(ull& acc, ull w, ull h) {
    asm("fma.rn.f32x2 %0, %1, %2, %0;" : "+l"(acc) : "l"(w), "l"(h));
}
__device__ __forceinline__ ull add2(ull a, ull b) {
    ull r; asm("add.rn.f32x2 %0, %1, %2;" : "=l"(r) : "l"(a), "l"(b)); return r;
}
__device__ __forceinline__ float2 unpack2(ull v) {
    float2 r; asm("mov.b64 {%0,%1}, %2;" : "=f"(r.x), "=f"(r.y) : "l"(v)); return r;
}

// 4 per-edge weights w[j..j+3] = sum_h h[h] * W[h*S + j..j+3]; W smem broadcast.
template <int S>
__device__ __forceinline__ float4 wchunk(const float* Wj, const ull* hh) {
    ull a0 = 0, a1 = 0, b0 = 0, b1 = 0;
#pragma unroll
    for (int h = 0; h < 32; h += 2) {
        const ulonglong2 w0 = *reinterpret_cast<const ulonglong2*>(Wj + h * S);
        const ulonglong2 w1 = *reinterpret_cast<const ulonglong2*>(Wj + (h + 1) * S);
        fma2(a0, w0.x, hh[h]);     fma2(a1, w0.y, hh[h]);
        fma2(b0, w1.x, hh[h + 1]); fma2(b1, w1.y, hh[h + 1]);
    }
    float2 lo = unpack2(add2(a0, b0));
    float2 hi = unpack2(add2(a1, b1));
    return make_float4(lo.x, lo.y, hi.x, hi.y);
}

// hidden layer from register es[16]: h = silu(es@W1*0.25)*(1/sqrt32), packed {h,h}
__device__ __forceinline__ void compute_h(const float* __restrict__ W1,
                                          const float* es, ull* hh) {
    ull acc2[16];
#pragma unroll
    for (int x = 0; x < 16; x++) acc2[x] = 0;
#pragma unroll
    for (int i = 0; i < 16; i++) {
        const ull ep = pack2(es[i], es[i]);
#pragma unroll
        for (int x = 0; x < 16; x += 2) {
            const ulonglong2 w = *reinterpret_cast<const ulonglong2*>(W1 + i * 32 + x * 2);
            fma2(acc2[x], w.x, ep);
            fma2(acc2[x + 1], w.y, ep);
        }
    }
#pragma unroll
    for (int x = 0; x < 16; x++) {
        float2 a = unpack2(acc2[x]);
        float t0 = a.x * 0.25f, t1 = a.y * 0.25f;
        float s0 = t0 / (1.f + __expf(-t0)) * INV_SQRT32;
        float s1 = t1 / (1.f + __expf(-t1)) * INV_SQRT32;
        hh[2 * x]     = pack2(s0, s0);
        hh[2 * x + 1] = pack2(s1, s1);
    }
}

// ---------------- tiny kernels ----------------
__global__ void k_detect(const int* __restrict__ ei32, int twoE) {
    __shared__ int any;
    if (threadIdx.x == 0) any = 0;
    __syncthreads();
    int nchk = (twoE < 2048 ? twoE : 2048);
    for (int i = threadIdx.x; i < nchk / 2; i += blockDim.x)
        if (ei32[2 * i + 1] != 0) any = 1;
    __syncthreads();
    if (threadIdx.x == 0) g_is64 = (any == 0);
}

__global__ void k_zero(float* __restrict__ out, int N) {
    int i = blockIdx.x * blockDim.x + threadIdx.x;
    if (i < N * 40) out[i] = 0.f;
    if (i < N) g_z[i] = 0.f;
}

__global__ void k_query(const float* __restrict__ node_ft, const float* __restrict__ wqs,
                        const float* __restrict__ wqv, const float* __restrict__ wds,
                        const float* __restrict__ wdv, int N) {
    int n = blockIdx.x * blockDim.x + threadIdx.x;
    if (n >= N) return;
    const float* x = node_ft + (size_t)n * 40;
    float xs[16], xv[24];
#pragma unroll
    for (int i = 0; i < 16; i++) xs[i] = x[i];
#pragma unroll
    for (int i = 0; i < 24; i++) xv[i] = x[16 + i];

    float qs[8];
#pragma unroll
    for (int o = 0; o < 8; o++) qs[o] = 0.f;
#pragma unroll
    for (int i = 0; i < 16; i++) {
        const float c = xs[i];
#pragma unroll
        for (int o = 0; o < 8; o++) qs[o] += c * __ldg(wqs + i * 8 + o);
    }
#pragma unroll
    for (int o = 0; o < 8; o++) qs[o] *= 0.25f;

    float qv[12];
#pragma unroll
    for (int o = 0; o < 12; o++) qv[o] = 0.f;
#pragma unroll
    for (int i = 0; i < 8; i++) {
#pragma unroll
        for (int o = 0; o < 4; o++) {
            const float w = __ldg(wqv + i * 4 + o);
            qv[o * 3 + 0] += xv[i * 3 + 0] * w;
            qv[o * 3 + 1] += xv[i * 3 + 1] * w;
            qv[o * 3 + 2] += xv[i * 3 + 2] * w;
        }
    }
#pragma unroll
    for (int o = 0; o < 12; o++) qv[o] *= INV_SQRT8;

    float qt[20];
#pragma unroll
    for (int o = 0; o < 20; o++) qt[o] = 0.f;
#pragma unroll
    for (int i = 0; i < 8; i++) {
        const float c = qs[i];
#pragma unroll
        for (int o = 0; o < 8; o++) qt[o] += c * __ldg(wds + i * 8 + o);
    }
#pragma unroll
    for (int i = 0; i < 4; i++) {
#pragma unroll
        for (int o = 0; o < 4; o++) {
            const float w = __ldg(wdv + i * 4 + o);
            qt[8 + o * 3 + 0] += qv[i * 3 + 0] * w;
            qt[8 + o * 3 + 1] += qv[i * 3 + 1] * w;
            qt[8 + o * 3 + 2] += qv[i * 3 + 2] * w;
        }
    }
    float* dst = g_qt + (size_t)n * 20;
#pragma unroll
    for (int t = 0; t < 20; t++) dst[t] = qt[t];
}

// ================= K kernel: full K TP + attention logit =================
// smem floats: W1[512] W2[32*320]
#define KK_SMEM ((512 + 10240) * 4)

__global__ __launch_bounds__(128, 4) void k_K(
    const float* __restrict__ node_ft, const void* __restrict__ ei,
    const float* __restrict__ edge_sh, const float* __restrict__ edge_scalars,
    const float* __restrict__ w1k, const float* __restrict__ w2k, int E) {
    extern __shared__ float sm[];
    const int tid = threadIdx.x;
    for (int i = tid * 4; i < 512;   i += 512) *(float4*)(sm + i) = *(const float4*)(w1k + i);
    for (int i = tid * 4; i < 10240; i += 512) *(float4*)(sm + 512 + i) = *(const float4*)(w2k + i);
    __syncthreads();

    const int e = blockIdx.x * 128 + tid;
    if (e >= E) return;
    const ll snd = eidx(ei, e);
    const ll rcv = eidx(ei, E + e);

    const float4 shq = *(const float4*)(edge_sh + (size_t)e * 4);
    const float shs = shq.x, sh0 = shq.y, sh1 = shq.z, sh2 = shq.w;

    // hidden layer
    ull hh[32];
    {
        float es[16];
        const float4* p = (const float4*)(edge_scalars + (size_t)e * 16);
#pragma unroll
        for (int t = 0; t < 4; t++) {
            float4 v = p[t];
            es[t * 4 + 0] = v.x; es[t * 4 + 1] = v.y; es[t * 4 + 2] = v.z; es[t * 4 + 3] = v.w;
        }
        compute_h(sm, es, hh);
    }

    const float* W = sm + 512;
    float accS[8], t3[4];
#pragma unroll
    for (int o = 0; o < 8; o++) accS[o] = 0.f;
#pragma unroll
    for (int o = 0; o < 4; o++) t3[o] = 0.f;

    // -------- phase A: xs (paths 1, 3) --------
    {
        float xs[16];
        const float4* q = (const float4*)(node_ft + (size_t)snd * 40);
#pragma unroll
        for (int t = 0; t < 4; t++) {
            float4 v = q[t];
            xs[t * 4 + 0] = v.x; xs[t * 4 + 1] = v.y; xs[t * 4 + 2] = v.z; xs[t * 4 + 3] = v.w;
        }
#pragma unroll
        for (int i = 0; i < 16; i++) {    // path1 -> scalars
            const float c = xs[i] * shs;
            float4 w0 = wchunk<320>(W + i * 8, hh);
            accS[0] += c * w0.x; accS[1] += c * w0.y; accS[2] += c * w0.z; accS[3] += c * w0.w;
            float4 w1 = wchunk<320>(W + i * 8 + 4, hh);
            accS[4] += c * w1.x; accS[5] += c * w1.y; accS[6] += c * w1.z; accS[7] += c * w1.w;
        }
#pragma unroll
        for (int i = 0; i < 16; i++) {    // path3 -> t3 (shv applied below)
            const float c = xs[i];
            float4 w = wchunk<320>(W + 192 + i * 4, hh);
            t3[0] += c * w.x; t3[1] += c * w.y; t3[2] += c * w.z; t3[3] += c * w.w;
        }
    }

    float kv[12];
#pragma unroll
    for (int o = 0; o < 4; o++) {
        kv[o * 3 + 0] = t3[o] * sh0;
        kv[o * 3 + 1] = t3[o] * sh1;
        kv[o * 3 + 2] = t3[o] * sh2;
    }

    // -------- phase B: xv (paths 2, 4, 5) --------
    {
        float xv[24];
        const float4* q = (const float4*)(node_ft + (size_t)snd * 40 + 16);
#pragma unroll
        for (int t = 0; t < 6; t++) {
            float4 v = q[t];
            xv[t * 4 + 0] = v.x; xv[t * 4 + 1] = v.y; xv[t * 4 + 2] = v.z; xv[t * 4 + 3] = v.w;
        }
#pragma unroll
        for (int i = 0; i < 8; i++) {     // path2 -> scalars
            const float c = (xv[i * 3] * sh0 + xv[i * 3 + 1] * sh1 + xv[i * 3 + 2] * sh2) * INV_SQRT3;
            float4 w0 = wchunk<320>(W + 128 + i * 8, hh);
            accS[0] += c * w0.x; accS[1] += c * w0.y; accS[2] += c * w0.z; accS[3] += c * w0.w;
            float4 w1 = wchunk<320>(W + 128 + i * 8 + 4, hh);
            accS[4] += c * w1.x; accS[5] += c * w1.y; accS[6] += c * w1.z; accS[7] += c * w1.w;
        }
#pragma unroll
        for (int i = 0; i < 8; i++) {     // path4 -> vectors (coeff xv*shs)
            const float c0 = xv[i * 3] * shs, c1 = xv[i * 3 + 1] * shs, c2 = xv[i * 3 + 2] * shs;
            float4 w = wchunk<320>(W + 256 + i * 4, hh);
            float wa[4] = {w.x, w.y, w.z, w.w};
#pragma unroll
            for (int t = 0; t < 4; t++) {
                kv[t * 3 + 0] += c0 * wa[t];
                kv[t * 3 + 1] += c1 * wa[t];
                kv[t * 3 + 2] += c2 * wa[t];
            }
        }
#pragma unroll
        for (int i = 0; i < 8; i++) {     // path5 -> vectors (cross)
            const float v0 = xv[i * 3], v1 = xv[i * 3 + 1], v2 = xv[i * 3 + 2];
            const float p0 = (v1 * sh2 - v2 * sh1) * INV_SQRT2;
            const float p1 = (v2 * sh0 - v0 * sh2) * INV_SQRT2;
            const float p2 = (v0 * sh1 - v1 * sh0) * INV_SQRT2;
            float4 w = wchunk<320>(W + 288 + i * 4, hh);
            float wa[4] = {w.x, w.y, w.z, w.w};
#pragma unroll
            for (int t = 0; t < 4; t++) {
                kv[t * 3 + 0] += p0 * wa[t];
                kv[t * 3 + 1] += p1 * wa[t];
                kv[t * 3 + 2] += p2 * wa[t];
            }
        }
    }

    // -------- attention logit --------
    const float* qt = g_qt + (size_t)rcv * 20;
    float dS = 0.f, dV = 0.f;
#pragma unroll
    for (int o = 0; o < 8; o++) dS += qt[o] * accS[o];
#pragma unroll
    for (int o = 0; o < 12; o++) dV += qt[8 + o] * kv[o];
    const float dot = (dS * INV_SQRT24 + dV * (INV_SQRT32 * INV_SQRT3)) * INV_SQRT80;
    const float exv = __expf(dot);
    g_ex[e] = exv;
    atomicAdd(&g_z[rcv], exv);
}

// ================= Vs kernel: all 16 V scalar outputs =================
// V weight slice j in [0,384): path1 j=i*16+o (i<16), path2 j=256+i*16+o (i<8)
// smem floats: W1[512] W2s[32*384]
#define VS_SMEM ((512 + 12288) * 4)

__global__ __launch_bounds__(128, 4) void k_Vs(
    const float* __restrict__ node_ft, const void* __restrict__ ei,
    const float* __restrict__ edge_sh, const float* __restrict__ edge_scalars,
    const float* __restrict__ w1v, const float* __restrict__ w2v, int E) {
    extern __shared__ float sm[];
    const int tid = threadIdx.x;
    for (int i = tid * 4; i < 512; i += 512) *(float4*)(sm + i) = *(const float4*)(w1v + i);
    {   // rows of 640 -> take first 384 of each row, coalesced float4
        float4* d4 = (float4*)(sm + 512);
        const float4* s4 = (const float4*)w2v;
        for (int idx = tid; idx < 32 * 96; idx += 128)
            d4[idx] = s4[(idx / 96) * 160 + (idx % 96)];
    }
    __syncthreads();

    const int e = blockIdx.x * 128 + tid;
    if (e >= E) return;
    const ll snd = eidx(ei, e);

    const float4 shq = *(const float4*)(edge_sh + (size_t)e * 4);
    const float shs = shq.x, sh0 = shq.y, sh1 = shq.z, sh2 = shq.w;

    ull hh[32];
    {
        float es[16];
        const float4* p = (const float4*)(edge_scalars + (size_t)e * 16);
#pragma unroll
        for (int t = 0; t < 4; t++) {
            float4 v = p[t];
            es[t * 4 + 0] = v.x; es[t * 4 + 1] = v.y; es[t * 4 + 2] = v.z; es[t * 4 + 3] = v.w;
        }
        compute_h(sm, es, hh);
    }

    const float* W = sm + 512;
    float accS[16];
#pragma unroll
    for (int o = 0; o < 16; o++) accS[o] = 0.f;

    {   // phase A: xs, path1
        float xs[16];
        const float4* q = (const float4*)(node_ft + (size_t)snd * 40);
#pragma unroll
        for (int t = 0; t < 4; t++) {
            float4 v = q[t];
            xs[t * 4 + 0] = v.x; xs[t * 4 + 1] = v.y; xs[t * 4 + 2] = v.z; xs[t * 4 + 3] = v.w;
        }
#pragma unroll
        for (int i = 0; i < 16; i++) {
            const float c = xs[i] * shs;
#pragma unroll
            for (int ob = 0; ob < 16; ob += 4) {
                float4 w = wchunk<384>(W + i * 16 + ob, hh);
                accS[ob + 0] += c * w.x; accS[ob + 1] += c * w.y;
                accS[ob + 2] += c * w.z; accS[ob + 3] += c * w.w;
            }
        }
    }
    {   // phase B: xv, path2
        float xv[24];
        const float4* q = (const float4*)(node_ft + (size_t)snd * 40 + 16);
#pragma unroll
        for (int t = 0; t < 6; t++) {
            float4 v = q[t];
            xv[t * 4 + 0] = v.x; xv[t * 4 + 1] = v.y; xv[t * 4 + 2] = v.z; xv[t * 4 + 3] = v.w;
        }
#pragma unroll
        for (int i = 0; i < 8; i++) {
            const float c = (xv[i * 3] * sh0 + xv[i * 3 + 1] * sh1 + xv[i * 3 + 2] * sh2) * INV_SQRT3;
#pragma unroll
            for (int ob = 0; ob < 16; ob += 4) {
                float4 w = wchunk<384>(W + 256 + i * 16 + ob, hh);
                accS[ob + 0] += c * w.x; accS[ob + 1] += c * w.y;
                accS[ob + 2] += c * w.z; accS[ob + 3] += c * w.w;
            }
        }
    }
    float* dst = g_vv + (size_t)e * 40;
#pragma unroll
    for (int t = 0; t < 4; t++)
        *(float4*)(dst + t * 4) = make_float4(accS[t * 4 + 0] * INV_SQRT24, accS[t * 4 + 1] * INV_SQRT24,
                                              accS[t * 4 + 2] * INV_SQRT24, accS[t * 4 + 3] * INV_SQRT24);
}

// ================= Vv kernel: 8 V vector outputs (paths 3,4,5) =================
// slice j in [384,640) -> local [0,256): path3 i*8+o, path4 128+i*8+o, path5 192+i*8+o
// smem floats: W1[512] W2c[32*256]
#define VV_SMEM ((512 + 8192) * 4)

__global__ __launch_bounds__(128, 4) void k_Vv(
    const float* __restrict__ node_ft, const void* __restrict__ ei,
    const float* __restrict__ edge_sh, const float* __restrict__ edge_scalars,
    const float* __restrict__ w1v, const float* __restrict__ w2v, int E) {
    extern __shared__ float sm[];
    const int tid = threadIdx.x;
    for (int i = tid * 4; i < 512; i += 512) *(float4*)(sm + i) = *(const float4*)(w1v + i);
    {   // rows of 640 -> take [384,640) of each row
        float4* d4 = (float4*)(sm + 512);
        const float4* s4 = (const float4*)w2v;
        for (int idx = tid; idx < 32 * 64; idx += 128)
            d4[idx] = s4[(idx / 64) * 160 + 96 + (idx % 64)];
    }
    __syncthreads();

    const int e = blockIdx.x * 128 + tid;
    if (e >= E) return;
    const ll snd = eidx(ei, e);

    const float4 shq = *(const float4*)(edge_sh + (size_t)e * 4);
    const float shs = shq.x, sh0 = shq.y, sh1 = shq.z, sh2 = shq.w;

    ull hh[32];
    {
        float es[16];
        const float4* p = (const float4*)(edge_scalars + (size_t)e * 16);
#pragma unroll
        for (int t = 0; t < 4; t++) {
            float4 v = p[t];
            es[t * 4 + 0] = v.x; es[t * 4 + 1] = v.y; es[t * 4 + 2] = v.z; es[t * 4 + 3] = v.w;
        }
        compute_h(sm, es, hh);
    }

    const float* W = sm + 512;
    float t3[8];
#pragma unroll
    for (int o = 0; o < 8; o++) t3[o] = 0.f;

    {   // phase A: xs, path3
        float xs[16];
        const float4* q = (const float4*)(node_ft + (size_t)snd * 40);
#pragma unroll
        for (int t = 0; t < 4; t++) {
            float4 v = q[t];
            xs[t * 4 + 0] = v.x; xs[t * 4 + 1] = v.y; xs[t * 4 + 2] = v.z; xs[t * 4 + 3] = v.w;
        }
#pragma unroll
        for (int i = 0; i < 16; i++) {
            const float c = xs[i];
            float4 w0 = wchunk<256>(W + i * 8, hh);
            t3[0] += c * w0.x; t3[1] += c * w0.y; t3[2] += c * w0.z; t3[3] += c * w0.w;
            float4 w1 = wchunk<256>(W + i * 8 + 4, hh);
            t3[4] += c * w1.x; t3[5] += c * w1.y; t3[6] += c * w1.z; t3[7] += c * w1.w;
        }
    }

    float vv[24];
#pragma unroll
    for (int o = 0; o < 8; o++) {
        vv[o * 3 + 0] = t3[o] * sh0;
        vv[o * 3 + 1] = t3[o] * sh1;
        vv[o * 3 + 2] = t3[o] * sh2;
    }

    {   // phase B: xv, paths 4, 5
        float xv[24];
        const float4* q = (const float4*)(node_ft + (size_t)snd * 40 + 16);
#pragma unroll
        for (int t = 0; t < 6; t++) {
            float4 v = q[t];
            xv[t * 4 + 0] = v.x; xv[t * 4 + 1] = v.y; xv[t * 4 + 2] = v.z; xv[t * 4 + 3] = v.w;
        }
#pragma unroll
        for (int i = 0; i < 8; i++) {     // path4
            const float c0 = xv[i * 3] * shs, c1 = xv[i * 3 + 1] * shs, c2 = xv[i * 3 + 2] * shs;
#pragma unroll
            for (int ob = 0; ob < 8; ob += 4) {
                float4 w = wchunk<256>(W + 128 + i * 8 + ob, hh);
                float wa[4] = {w.x, w.y, w.z, w.w};
#pragma unroll
                for (int t = 0; t < 4; t++) {
                    vv[(ob + t) * 3 + 0] += c0 * wa[t];
                    vv[(ob + t) * 3 + 1] += c1 * wa[t];
                    vv[(ob + t) * 3 + 2] += c2 * wa[t];
                }
            }
        }
#pragma unroll
        for (int i = 0; i < 8; i++) {     // path5
            const float v0 = xv[i * 3], v1 = xv[i * 3 + 1], v2 = xv[i * 3 + 2];
            const float p0 = (v1 * sh2 - v2 * sh1) * INV_SQRT2;
            const float p1 = (v2 * sh0 - v0 * sh2) * INV_SQRT2;
            const float p2 = (v0 * sh1 - v1 * sh0) * INV_SQRT2;
#pragma unroll
            for (int ob = 0; ob < 8; ob += 4) {
                float4 w = wchunk<256>(W + 192 + i * 8 + ob, hh);
                float wa[4] = {w.x, w.y, w.z, w.w};
#pragma unroll
                for (int t = 0; t < 4; t++) {
                    vv[(ob + t) * 3 + 0] += p0 * wa[t];
                    vv[(ob + t) * 3 + 1] += p1 * wa[t];
                    vv[(ob + t) * 3 + 2] += p2 * wa[t];
                }
            }
        }
    }

    float* dst = g_vv + (size_t)e * 40 + 16;
#pragma unroll
    for (int t = 0; t < 6; t++)
        *(float4*)(dst + t * 4) = make_float4(vv[t * 4 + 0] * INV_SQRT32, vv[t * 4 + 1] * INV_SQRT32,
                                              vv[t * 4 + 2] * INV_SQRT32, vv[t * 4 + 3] * INV_SQRT32);
}

// ---------------- scatter: softmax normalize + vector reduction ----------------
__global__ void k_scatter(const void* __restrict__ ei, float* __restrict__ out, int E) {
    int e = blockIdx.x * blockDim.x + threadIdx.x;
    if (e >= E) return;
    const ll r = eidx(ei, E + e);
    const float a = sqrtf(g_ex[e] / g_z[r]);
    const float4* v = (const float4*)(g_vv + (size_t)e * 40);
    float* o = out + (size_t)r * 40;
#pragma unroll
    for (int t = 0; t < 10; t++) {
        float4 w = v[t];
        asm volatile("red.global.add.v4.f32 [%0], {%1, %2, %3, %4};"
                     :: "l"(o + t * 4), "f"(a * w.x), "f"(a * w.y), "f"(a * w.z), "f"(a * w.w)
                     : "memory");
    }
}

extern "C" void kernel_launch(void* const* d_in, const int* in_sizes, int n_in,
                              void* d_out, int out_size) {
    const float* node_ft      = (const float*)d_in[0];
    const void*  ei           = d_in[1];
    const float* edge_sh      = (const float*)d_in[2];
    const float* edge_scalars = (const float*)d_in[3];
    const float* wqs          = (const float*)d_in[4];
    const float* wqv          = (const float*)d_in[5];
    const float* fckw1        = (const float*)d_in[6];
    const float* fckw2        = (const float*)d_in[7];
    const float* fcvw1        = (const float*)d_in[8];
    const float* fcvw2        = (const float*)d_in[9];
    const float* wds          = (const float*)d_in[10];
    const float* wdv          = (const float*)d_in[11];
    float* out = (float*)d_out;

    const int N = in_sizes[0] / 40;
    const int E = in_sizes[1] / 2;
    const int gE = (E + 127) / 128;

    cudaFuncSetAttribute(k_K,  cudaFuncAttributeMaxDynamicSharedMemorySize, KK_SMEM);
    cudaFuncSetAttribute(k_Vs, cudaFuncAttributeMaxDynamicSharedMemorySize, VS_SMEM);
    cudaFuncSetAttribute(k_Vv, cudaFuncAttributeMaxDynamicSharedMemorySize, VV_SMEM);

    k_detect<<<1, 256>>>((const int*)ei, 2 * E);
    k_zero<<<(N * 40 + 255) / 256, 256>>>(out, N);
    k_query<<<(N + 255) / 256, 256>>>(node_ft, wqs, wqv, wds, wdv, N);
    k_K<<<gE, 128, KK_SMEM>>>(node_ft, ei, edge_sh, edge_scalars, fckw1, fckw2, E);
    k_Vs<<<gE, 128, VS_SMEM>>>(node_ft, ei, edge_sh, edge_scalars, fcvw1, fcvw2, E);
    k_Vv<<<gE, 128, VV_SMEM>>>(node_ft, ei, edge_sh, edge_scalars, fcvw1, fcvw2, E);
    k_scatter<<<(E + 255) / 256, 256>>>(ei, out, E);
}

// round 7
// speedup vs baseline: 1.7764x; 1.0506x over previous
#include <cuda_runtime.h>
#include <math.h>

typedef unsigned long long ull;
typedef long long ll;

#define NMAX 10000
#define EMAX 100000

__device__ __align__(16) float g_qt[NMAX * 20];  // per-node pre-rotated query
__device__ float g_z[NMAX];                      // softmax denominators
__device__ float g_ex[EMAX];                     // per-edge exp(dot)
__device__ __align__(16) float g_vv[EMAX * 40];  // per-edge value irreps
__device__ int g_is64;                           // edge_index dtype flag

#define INV_SQRT3  0.5773502691896258f
#define INV_SQRT2  0.7071067811865476f
#define INV_SQRT8  0.35355339059327373f
#define INV_SQRT24 0.2041241452319315f
#define INV_SQRT32 0.17677669529663687f
#define INV_SQRT80 0.11180339887498948f

__device__ __forceinline__ ll eidx(const void* ei, int pos) {
    if (g_is64) return ((const ll*)ei)[pos];
    return (ll)((const int*)ei)[pos];
}

// ---------------- packed f32x2 helpers ----------------
__device__ __forceinline__ ull pack2(float a, float b) {
    ull r; asm("mov.b64 %0, {%1,%2};" : "=l"(r) : "f"(a), "f"(b)); return r;
}
__device__ __forceinline__ void fma2(ull& acc, ull w, ull h) {
    asm("fma.rn.f32x2 %0, %1, %2, %0;" : "+l"(acc) : "l"(w), "l"(h));
}
__device__ __forceinline__ ull add2(ull a, ull b) {
    ull r; asm("add.rn.f32x2 %0, %1, %2;" : "=l"(r) : "l"(a), "l"(b)); return r;
}
__device__ __forceinline__ float2 unpack2(ull v) {
    float2 r; asm("mov.b64 {%0,%1}, %2;" : "=f"(r.x), "=f"(r.y) : "l"(v)); return r;
}
// pair combine: sum value with partner lane (lane^1)
__device__ __forceinline__ float comb(float v) {
    return v + __shfl_xor_sync(0xffffffffu, v, 1);
}

// half-h weight chunk: 4 consecutive per-edge weights from THIS lane's 16 hidden units.
// W2 smem is pair-interleaved: float4 unit u = (h_local*S4 + j4)*2 + par.
template <int S4>
__device__ __forceinline__ float4 wchunk16(const float* W2, int j4, const ull* hh, int par) {
    ull a0 = 0, a1 = 0, b0 = 0, b1 = 0;
    const float* base = W2 + j4 * 8 + par * 4;
#pragma unroll
    for (int h = 0; h < 16; h += 2) {
        const ulonglong2 w0 = *reinterpret_cast<const ulonglong2*>(base + h * (S4 * 8));
        const ulonglong2 w1 = *reinterpret_cast<const ulonglong2*>(base + (h + 1) * (S4 * 8));
        fma2(a0, w0.x, hh[h]);     fma2(a1, w0.y, hh[h]);
        fma2(b0, w1.x, hh[h + 1]); fma2(b1, w1.y, hh[h + 1]);
    }
    float2 lo = unpack2(add2(a0, b0));
    float2 hi = unpack2(add2(a1, b1));
    return make_float4(lo.x, lo.y, hi.x, hi.y);
}

// hidden half: this lane computes cols [par*16, par*16+16) of h = silu(es@W1*0.25)/sqrt32
__device__ __forceinline__ void compute_h16(const float* __restrict__ W1,
                                            const float* es, ull* hh, int par) {
    ull acc2[8];
#pragma unroll
    for (int x = 0; x < 8; x++) acc2[x] = 0;
    const float* base = W1 + par * 16;
#pragma unroll
    for (int i = 0; i < 16; i++) {
        const ull ep = pack2(es[i], es[i]);
#pragma unroll
        for (int xl = 0; xl < 8; xl += 2) {
            const ulonglong2 w = *reinterpret_cast<const ulonglong2*>(base + i * 32 + xl * 2);
            fma2(acc2[xl], w.x, ep);
            fma2(acc2[xl + 1], w.y, ep);
        }
    }
#pragma unroll
    for (int x = 0; x < 8; x++) {
        float2 a = unpack2(acc2[x]);
        float t0 = a.x * 0.25f, t1 = a.y * 0.25f;
        float s0 = t0 / (1.f + __expf(-t0)) * INV_SQRT32;
        float s1 = t1 / (1.f + __expf(-t1)) * INV_SQRT32;
        hh[2 * x]     = pack2(s0, s0);
        hh[2 * x + 1] = pack2(s1, s1);
    }
}

// load es[16] for edge e
__device__ __forceinline__ void load_es(float* es, const float* __restrict__ edge_scalars, int e) {
    const float4* p = (const float4*)(edge_scalars + (size_t)e * 16);
#pragma unroll
    for (int t = 0; t < 4; t++) {
        float4 v = p[t];
        es[t * 4 + 0] = v.x; es[t * 4 + 1] = v.y; es[t * 4 + 2] = v.z; es[t * 4 + 3] = v.w;
    }
}

// ---------------- tiny kernels ----------------
__global__ void k_detect(const int* __restrict__ ei32, int twoE) {
    __shared__ int any;
    if (threadIdx.x == 0) any = 0;
    __syncthreads();
    int nchk = (twoE < 2048 ? twoE : 2048);
    for (int i = threadIdx.x; i < nchk / 2; i += blockDim.x)
        if (ei32[2 * i + 1] != 0) any = 1;
    __syncthreads();
    if (threadIdx.x == 0) g_is64 = (any == 0);
}

__global__ void k_zero(float* __restrict__ out, int N) {
    int i = blockIdx.x * blockDim.x + threadIdx.x;
    if (i < N * 40) out[i] = 0.f;
    if (i < N) g_z[i] = 0.f;
}

__global__ void k_query(const float* __restrict__ node_ft, const float* __restrict__ wqs,
                        const float* __restrict__ wqv, const float* __restrict__ wds,
                        const float* __restrict__ wdv, int N) {
    int n = blockIdx.x * blockDim.x + threadIdx.x;
    if (n >= N) return;
    const float* x = node_ft + (size_t)n * 40;
    float xs[16], xv[24];
#pragma unroll
    for (int i = 0; i < 16; i++) xs[i] = x[i];
#pragma unroll
    for (int i = 0; i < 24; i++) xv[i] = x[16 + i];

    float qs[8];
#pragma unroll
    for (int o = 0; o < 8; o++) qs[o] = 0.f;
#pragma unroll
    for (int i = 0; i < 16; i++) {
        const float c = xs[i];
#pragma unroll
        for (int o = 0; o < 8; o++) qs[o] += c * __ldg(wqs + i * 8 + o);
    }
#pragma unroll
    for (int o = 0; o < 8; o++) qs[o] *= 0.25f;

    float qv[12];
#pragma unroll
    for (int o = 0; o < 12; o++) qv[o] = 0.f;
#pragma unroll
    for (int i = 0; i < 8; i++) {
#pragma unroll
        for (int o = 0; o < 4; o++) {
            const float w = __ldg(wqv + i * 4 + o);
            qv[o * 3 + 0] += xv[i * 3 + 0] * w;
            qv[o * 3 + 1] += xv[i * 3 + 1] * w;
            qv[o * 3 + 2] += xv[i * 3 + 2] * w;
        }
    }
#pragma unroll
    for (int o = 0; o < 12; o++) qv[o] *= INV_SQRT8;

    float qt[20];
#pragma unroll
    for (int o = 0; o < 20; o++) qt[o] = 0.f;
#pragma unroll
    for (int i = 0; i < 8; i++) {
        const float c = qs[i];
#pragma unroll
        for (int o = 0; o < 8; o++) qt[o] += c * __ldg(wds + i * 8 + o);
    }
#pragma unroll
    for (int i = 0; i < 4; i++) {
#pragma unroll
        for (int o = 0; o < 4; o++) {
            const float w = __ldg(wdv + i * 4 + o);
            qt[8 + o * 3 + 0] += qv[i * 3 + 0] * w;
            qt[8 + o * 3 + 1] += qv[i * 3 + 1] * w;
            qt[8 + o * 3 + 2] += qv[i * 3 + 2] * w;
        }
    }
    float* dst = g_qt + (size_t)n * 20;
#pragma unroll
    for (int t = 0; t < 20; t++) dst[t] = qt[t];
}

// ================= K kernel: full K TP + logit; 2 lanes per edge =================
// smem floats: W1[512] W2 interleaved[32*320]
#define KK_SMEM ((512 + 10240) * 4)

__global__ __launch_bounds__(128, 4) void k_K(
    const float* __restrict__ node_ft, const void* __restrict__ ei,
    const float* __restrict__ edge_sh, const float* __restrict__ edge_scalars,
    const float* __restrict__ w1k, const float* __restrict__ w2k, int E) {
    extern __shared__ float sm[];
    const int tid = threadIdx.x;
    for (int i = tid * 4; i < 512; i += 512) *(float4*)(sm + i) = *(const float4*)(w1k + i);
    {
        float4* d4 = (float4*)(sm + 512);
        const float4* s4 = (const float4*)w2k;
        for (int g = tid; g < 32 * 80; g += 128) {
            int h = g / 80, j4 = g % 80;
            d4[((h & 15) * 80 + j4) * 2 + (h >> 4)] = s4[g];
        }
    }
    __syncthreads();

    int e = (blockIdx.x * 128 + tid) >> 1;
    const int par = tid & 1;
    const bool valid = (e < E);
    if (!valid) e = E - 1;

    const ll snd = eidx(ei, e);
    const ll rcv = eidx(ei, E + e);

    const float4 shq = *(const float4*)(edge_sh + (size_t)e * 4);
    const float shs = shq.x, sh0 = shq.y, sh1 = shq.z, sh2 = shq.w;

    ull hh[16];
    {
        float es[16];
        load_es(es, edge_scalars, e);
        compute_h16(sm, es, hh, par);
    }

    const float* W = sm + 512;
    float accS[8], t3[4];
#pragma unroll
    for (int o = 0; o < 8; o++) accS[o] = 0.f;
#pragma unroll
    for (int o = 0; o < 4; o++) t3[o] = 0.f;

    // -------- phase A: xs (paths 1, 3) --------
    {
        float xs[16];
        const float4* q = (const float4*)(node_ft + (size_t)snd * 40);
#pragma unroll
        for (int t = 0; t < 4; t++) {
            float4 v = q[t];
            xs[t * 4 + 0] = v.x; xs[t * 4 + 1] = v.y; xs[t * 4 + 2] = v.z; xs[t * 4 + 3] = v.w;
        }
#pragma unroll
        for (int i = 0; i < 16; i++) {    // path1 -> scalars (cols i*8 .. i*8+8)
            const float c = xs[i] * shs;
            float4 w0 = wchunk16<80>(W, i * 2, hh, par);
            accS[0] += c * w0.x; accS[1] += c * w0.y; accS[2] += c * w0.z; accS[3] += c * w0.w;
            float4 w1 = wchunk16<80>(W, i * 2 + 1, hh, par);
            accS[4] += c * w1.x; accS[5] += c * w1.y; accS[6] += c * w1.z; accS[7] += c * w1.w;
        }
#pragma unroll
        for (int i = 0; i < 16; i++) {    // path3 -> t3 (cols 192 + i*4)
            const float c = xs[i];
            float4 w = wchunk16<80>(W, 48 + i, hh, par);
            t3[0] += c * w.x; t3[1] += c * w.y; t3[2] += c * w.z; t3[3] += c * w.w;
        }
    }

    float kv[12];
#pragma unroll
    for (int o = 0; o < 4; o++) {
        kv[o * 3 + 0] = t3[o] * sh0;
        kv[o * 3 + 1] = t3[o] * sh1;
        kv[o * 3 + 2] = t3[o] * sh2;
    }

    // -------- phase B: xv (paths 2, 4, 5) --------
    {
        float xv[24];
        const float4* q = (const float4*)(node_ft + (size_t)snd * 40 + 16);
#pragma unroll
        for (int t = 0; t < 6; t++) {
            float4 v = q[t];
            xv[t * 4 + 0] = v.x; xv[t * 4 + 1] = v.y; xv[t * 4 + 2] = v.z; xv[t * 4 + 3] = v.w;
        }
#pragma unroll
        for (int i = 0; i < 8; i++) {     // path2 -> scalars (cols 128 + i*8)
            const float c = (xv[i * 3] * sh0 + xv[i * 3 + 1] * sh1 + xv[i * 3 + 2] * sh2) * INV_SQRT3;
            float4 w0 = wchunk16<80>(W, 32 + i * 2, hh, par);
            accS[0] += c * w0.x; accS[1] += c * w0.y; accS[2] += c * w0.z; accS[3] += c * w0.w;
            float4 w1 = wchunk16<80>(W, 32 + i * 2 + 1, hh, par);
            accS[4] += c * w1.x; accS[5] += c * w1.y; accS[6] += c * w1.z; accS[7] += c * w1.w;
        }
#pragma unroll
        for (int i = 0; i < 8; i++) {     // path4 -> vectors (cols 256 + i*4)
            const float c0 = xv[i * 3] * shs, c1 = xv[i * 3 + 1] * shs, c2 = xv[i * 3 + 2] * shs;
            float4 w = wchunk16<80>(W, 64 + i, hh, par);
            float wa[4] = {w.x, w.y, w.z, w.w};
#pragma unroll
            for (int t = 0; t < 4; t++) {
                kv[t * 3 + 0] += c0 * wa[t];
                kv[t * 3 + 1] += c1 * wa[t];
                kv[t * 3 + 2] += c2 * wa[t];
            }
        }
#pragma unroll
        for (int i = 0; i < 8; i++) {     // path5 -> vectors (cols 288 + i*4)
            const float v0 = xv[i * 3], v1 = xv[i * 3 + 1], v2 = xv[i * 3 + 2];
            const float p0 = (v1 * sh2 - v2 * sh1) * INV_SQRT2;
            const float p1 = (v2 * sh0 - v0 * sh2) * INV_SQRT2;
            const float p2 = (v0 * sh1 - v1 * sh0) * INV_SQRT2;
            float4 w = wchunk16<80>(W, 72 + i, hh, par);
            float wa[4] = {w.x, w.y, w.z, w.w};
#pragma unroll
            for (int t = 0; t < 4; t++) {
                kv[t * 3 + 0] += p0 * wa[t];
                kv[t * 3 + 1] += p1 * wa[t];
                kv[t * 3 + 2] += p2 * wa[t];
            }
        }
    }

    // -------- combine lane pair, logit on even lane --------
#pragma unroll
    for (int o = 0; o < 8; o++) accS[o] = comb(accS[o]);
#pragma unroll
    for (int o = 0; o < 12; o++) kv[o] = comb(kv[o]);

    if (par == 0 && valid) {
        const float* qt = g_qt + (size_t)rcv * 20;
        float dS = 0.f, dV = 0.f;
#pragma unroll
        for (int o = 0; o < 8; o++) dS += qt[o] * accS[o];
#pragma unroll
        for (int o = 0; o < 12; o++) dV += qt[8 + o] * kv[o];
        const float dot = (dS * INV_SQRT24 + dV * (INV_SQRT32 * INV_SQRT3)) * INV_SQRT80;
        const float exv = __expf(dot);
        g_ex[e] = exv;
        atomicAdd(&g_z[rcv], exv);
    }
}

// ================= Vs kernel: 16 V scalar outputs; 2 lanes per edge =================
// V slice j in [0,384): path1 j=i*16+o, path2 j=256+i*16+o
// smem floats: W1[512] W2 interleaved[32*384]
#define VS_SMEM ((512 + 12288) * 4)

__global__ __launch_bounds__(128, 4) void k_Vs(
    const float* __restrict__ node_ft, const void* __restrict__ ei,
    const float* __restrict__ edge_sh, const float* __restrict__ edge_scalars,
    const float* __restrict__ w1v, const float* __restrict__ w2v, int E) {
    extern __shared__ float sm[];
    const int tid = threadIdx.x;
    for (int i = tid * 4; i < 512; i += 512) *(float4*)(sm + i) = *(const float4*)(w1v + i);
    {
        float4* d4 = (float4*)(sm + 512);
        const float4* s4 = (const float4*)w2v;   // rows of 160 float4; take first 96
        for (int g = tid; g < 32 * 96; g += 128) {
            int h = g / 96, j4 = g % 96;
            d4[((h & 15) * 96 + j4) * 2 + (h >> 4)] = s4[h * 160 + j4];
        }
    }
    __syncthreads();

    int e = (blockIdx.x * 128 + tid) >> 1;
    const int par = tid & 1;
    const bool valid = (e < E);
    if (!valid) e = E - 1;
    const ll snd = eidx(ei, e);

    const float4 shq = *(const float4*)(edge_sh + (size_t)e * 4);
    const float shs = shq.x, sh0 = shq.y, sh1 = shq.z, sh2 = shq.w;

    ull hh[16];
    {
        float es[16];
        load_es(es, edge_scalars, e);
        compute_h16(sm, es, hh, par);
    }

    const float* W = sm + 512;
    float accS[16];
#pragma unroll
    for (int o = 0; o < 16; o++) accS[o] = 0.f;

    {   // phase A: xs, path1 (cols i*16)
        float xs[16];
        const float4* q = (const float4*)(node_ft + (size_t)snd * 40);
#pragma unroll
        for (int t = 0; t < 4; t++) {
            float4 v = q[t];
            xs[t * 4 + 0] = v.x; xs[t * 4 + 1] = v.y; xs[t * 4 + 2] = v.z; xs[t * 4 + 3] = v.w;
        }
#pragma unroll
        for (int i = 0; i < 16; i++) {
            const float c = xs[i] * shs;
#pragma unroll
            for (int ob = 0; ob < 4; ob++) {
                float4 w = wchunk16<96>(W, i * 4 + ob, hh, par);
                accS[ob * 4 + 0] += c * w.x; accS[ob * 4 + 1] += c * w.y;
                accS[ob * 4 + 2] += c * w.z; accS[ob * 4 + 3] += c * w.w;
            }
        }
    }
    {   // phase B: xv, path2 (cols 256 + i*16)
        float xv[24];
        const float4* q = (const float4*)(node_ft + (size_t)snd * 40 + 16);
#pragma unroll
        for (int t = 0; t < 6; t++) {
            float4 v = q[t];
            xv[t * 4 + 0] = v.x; xv[t * 4 + 1] = v.y; xv[t * 4 + 2] = v.z; xv[t * 4 + 3] = v.w;
        }
#pragma unroll
        for (int i = 0; i < 8; i++) {
            const float c = (xv[i * 3] * sh0 + xv[i * 3 + 1] * sh1 + xv[i * 3 + 2] * sh2) * INV_SQRT3;
#pragma unroll
            for (int ob = 0; ob < 4; ob++) {
                float4 w = wchunk16<96>(W, 64 + i * 4 + ob, hh, par);
                accS[ob * 4 + 0] += c * w.x; accS[ob * 4 + 1] += c * w.y;
                accS[ob * 4 + 2] += c * w.z; accS[ob * 4 + 3] += c * w.w;
            }
        }
    }
#pragma unroll
    for (int o = 0; o < 16; o++) accS[o] = comb(accS[o]);
    if (par == 0 && valid) {
        float* dst = g_vv + (size_t)e * 40;
#pragma unroll
        for (int t = 0; t < 4; t++)
            *(float4*)(dst + t * 4) = make_float4(accS[t * 4 + 0] * INV_SQRT24, accS[t * 4 + 1] * INV_SQRT24,
                                                  accS[t * 4 + 2] * INV_SQRT24, accS[t * 4 + 3] * INV_SQRT24);
    }
}

// ================= Vv kernel: 8 V vector outputs; 2 lanes per edge =================
// slice j in [384,640) -> local [0,256): path3 i*8+o, path4 128+i*8+o, path5 192+i*8+o
// smem floats: W1[512] W2 interleaved[32*256]
#define VV_SMEM ((512 + 8192) * 4)

__global__ __launch_bounds__(128, 4) void k_Vv(
    const float* __restrict__ node_ft, const void* __restrict__ ei,
    const float* __restrict__ edge_sh, const float* __restrict__ edge_scalars,
    const float* __restrict__ w1v, const float* __restrict__ w2v, int E) {
    extern __shared__ float sm[];
    const int tid = threadIdx.x;
    for (int i = tid * 4; i < 512; i += 512) *(float4*)(sm + i) = *(const float4*)(w1v + i);
    {
        float4* d4 = (float4*)(sm + 512);
        const float4* s4 = (const float4*)w2v;   // rows of 160 float4; take [96,160)
        for (int g = tid; g < 32 * 64; g += 128) {
            int h = g / 64, j4 = g % 64;
            d4[((h & 15) * 64 + j4) * 2 + (h >> 4)] = s4[h * 160 + 96 + j4];
        }
    }
    __syncthreads();

    int e = (blockIdx.x * 128 + tid) >> 1;
    const int par = tid & 1;
    const bool valid = (e < E);
    if (!valid) e = E - 1;
    const ll snd = eidx(ei, e);

    const float4 shq = *(const float4*)(edge_sh + (size_t)e * 4);
    const float shs = shq.x, sh0 = shq.y, sh1 = shq.z, sh2 = shq.w;

    ull hh[16];
    {
        float es[16];
        load_es(es, edge_scalars, e);
        compute_h16(sm, es, hh, par);
    }

    const float* W = sm + 512;
    float t3[8];
#pragma unroll
    for (int o = 0; o < 8; o++) t3[o] = 0.f;

    {   // phase A: xs, path3
        float xs[16];
        const float4* q = (const float4*)(node_ft + (size_t)snd * 40);
#pragma unroll
        for (int t = 0; t < 4; t++) {
            float4 v = q[t];
            xs[t * 4 + 0] = v.x; xs[t * 4 + 1] = v.y; xs[t * 4 + 2] = v.z; xs[t * 4 + 3] = v.w;
        }
#pragma unroll
        for (int i = 0; i < 16; i++) {
            const float c = xs[i];
            float4 w0 = wchunk16<64>(W, i * 2, hh, par);
            t3[0] += c * w0.x; t3[1] += c * w0.y; t3[2] += c * w0.z; t3[3] += c * w0.w;
            float4 w1 = wchunk16<64>(W, i * 2 + 1, hh, par);
            t3[4] += c * w1.x; t3[5] += c * w1.y; t3[6] += c * w1.z; t3[7] += c * w1.w;
        }
    }

    float vv[24];
#pragma unroll
    for (int o = 0; o < 8; o++) {
        vv[o * 3 + 0] = t3[o] * sh0;
        vv[o * 3 + 1] = t3[o] * sh1;
        vv[o * 3 + 2] = t3[o] * sh2;
    }

    {   // phase B: xv, paths 4, 5
        float xv[24];
        const float4* q = (const float4*)(node_ft + (size_t)snd * 40 + 16);
#pragma unroll
        for (int t = 0; t < 6; t++) {
            float4 v = q[t];
            xv[t * 4 + 0] = v.x; xv[t * 4 + 1] = v.y; xv[t * 4 + 2] = v.z; xv[t * 4 + 3] = v.w;
        }
#pragma unroll
        for (int i = 0; i < 8; i++) {     // path4 (cols 128 + i*8)
            const float c0 = xv[i * 3] * shs, c1 = xv[i * 3 + 1] * shs, c2 = xv[i * 3 + 2] * shs;
#pragma unroll
            for (int ob = 0; ob < 2; ob++) {
                float4 w = wchunk16<64>(W, 32 + i * 2 + ob, hh, par);
                float wa[4] = {w.x, w.y, w.z, w.w};
#pragma unroll
                for (int t = 0; t < 4; t++) {
                    vv[(ob * 4 + t) * 3 + 0] += c0 * wa[t];
                    vv[(ob * 4 + t) * 3 + 1] += c1 * wa[t];
                    vv[(ob * 4 + t) * 3 + 2] += c2 * wa[t];
                }
            }
        }
#pragma unroll
        for (int i = 0; i < 8; i++) {     // path5 (cols 192 + i*8)
            const float v0 = xv[i * 3], v1 = xv[i * 3 + 1], v2 = xv[i * 3 + 2];
            const float p0 = (v1 * sh2 - v2 * sh1) * INV_SQRT2;
            const float p1 = (v2 * sh0 - v0 * sh2) * INV_SQRT2;
            const float p2 = (v0 * sh1 - v1 * sh0) * INV_SQRT2;
#pragma unroll
            for (int ob = 0; ob < 2; ob++) {
                float4 w = wchunk16<64>(W, 48 + i * 2 + ob, hh, par);
                float wa[4] = {w.x, w.y, w.z, w.w};
#pragma unroll
                for (int t = 0; t < 4; t++) {
                    vv[(ob * 4 + t) * 3 + 0] += p0 * wa[t];
                    vv[(ob * 4 + t) * 3 + 1] += p1 * wa[t];
                    vv[(ob * 4 + t) * 3 + 2] += p2 * wa[t];
                }
            }
        }
    }

#pragma unroll
    for (int o = 0; o < 24; o++) vv[o] = comb(vv[o]);
    if (par == 0 && valid) {
        float* dst = g_vv + (size_t)e * 40 + 16;
#pragma unroll
        for (int t = 0; t < 6; t++)
            *(float4*)(dst + t * 4) = make_float4(vv[t * 4 + 0] * INV_SQRT32, vv[t * 4 + 1] * INV_SQRT32,
                                                  vv[t * 4 + 2] * INV_SQRT32, vv[t * 4 + 3] * INV_SQRT32);
    }
}

// ---------------- scatter: softmax normalize + vector reduction ----------------
__global__ void k_scatter(const void* __restrict__ ei, float* __restrict__ out, int E) {
    int e = blockIdx.x * blockDim.x + threadIdx.x;
    if (e >= E) return;
    const ll r = eidx(ei, E + e);
    const float a = sqrtf(g_ex[e] / g_z[r]);
    const float4* v = (const float4*)(g_vv + (size_t)e * 40);
    float* o = out + (size_t)r * 40;
#pragma unroll
    for (int t = 0; t < 10; t++) {
        float4 w = v[t];
        asm volatile("red.global.add.v4.f32 [%0], {%1, %2, %3, %4};"
                     :: "l"(o + t * 4), "f"(a * w.x), "f"(a * w.y), "f"(a * w.z), "f"(a * w.w)
                     : "memory");
    }
}

extern "C" void kernel_launch(void* const* d_in, const int* in_sizes, int n_in,
                              void* d_out, int out_size) {
    const float* node_ft      = (const float*)d_in[0];
    const void*  ei           = d_in[1];
    const float* edge_sh      = (const float*)d_in[2];
    const float* edge_scalars = (const float*)d_in[3];
    const float* wqs          = (const float*)d_in[4];
    const float* wqv          = (const float*)d_in[5];
    const float* fckw1        = (const float*)d_in[6];
    const float* fckw2        = (const float*)d_in[7];
    const float* fcvw1        = (const float*)d_in[8];
    const float* fcvw2        = (const float*)d_in[9];
    const float* wds          = (const float*)d_in[10];
    const float* wdv          = (const float*)d_in[11];
    float* out = (float*)d_out;

    const int N = in_sizes[0] / 40;
    const int E = in_sizes[1] / 2;
    const int gE2 = (E + 63) / 64;     // 64 edges per 128-thread block (2 lanes/edge)

    cudaFuncSetAttribute(k_K,  cudaFuncAttributeMaxDynamicSharedMemorySize, KK_SMEM);
    cudaFuncSetAttribute(k_Vs, cudaFuncAttributeMaxDynamicSharedMemorySize, VS_SMEM);
    cudaFuncSetAttribute(k_Vv, cudaFuncAttributeMaxDynamicSharedMemorySize, VV_SMEM);

    k_detect<<<1, 256>>>((const int*)ei, 2 * E);
    k_zero<<<(N * 40 + 255) / 256, 256>>>(out, N);
    k_query<<<(N + 255) / 256, 256>>>(node_ft, wqs, wqv, wds, wdv, N);
    k_K<<<gE2, 128, KK_SMEM>>>(node_ft, ei, edge_sh, edge_scalars, fckw1, fckw2, E);
    k_Vs<<<gE2, 128, VS_SMEM>>>(node_ft, ei, edge_sh, edge_scalars, fcvw1, fcvw2, E);
    k_Vv<<<gE2, 128, VV_SMEM>>>(node_ft, ei, edge_sh, edge_scalars, fcvw1, fcvw2, E);
    k_scatter<<<(E + 255) / 256, 256>>>(ei, out, E);
}